// round 1
// baseline (speedup 1.0000x reference)
#include <cuda_runtime.h>

#define N_NODES 50000
#define N_EDGES 800000
#define F 256

// ---------------- scratch (static device globals; no runtime alloc) -------
__device__ float g_buf[(size_t)N_NODES * F];   // dinv-scaled GEMM output
__device__ float h_buf[(size_t)N_NODES * F];   // layer-1 activations
__device__ int   g_counts[N_NODES];
__device__ int   g_rowstart[N_NODES + 1];
__device__ int   g_cursor[N_NODES];
__device__ float g_dinv[N_NODES];
__device__ int   g_srcsorted[N_EDGES];

// ---------------- graph preprocessing -------------------------------------
__global__ void init_counts_kernel() {
    int i = blockIdx.x * blockDim.x + threadIdx.x;
    if (i < N_NODES) g_counts[i] = 0;
}

__global__ void hist_kernel(const int* __restrict__ dstp) {
    int e = blockIdx.x * blockDim.x + threadIdx.x;
    if (e < N_EDGES) atomicAdd(&g_counts[dstp[e]], 1);
}

// single-block exclusive scan of g_counts -> g_rowstart (50k elements)
__global__ void scan_kernel() {
    __shared__ int warpsum[32];
    const int lane = threadIdx.x & 31;
    const int w    = threadIdx.x >> 5;
    int carry = 0;
    for (int base = 0; base < N_NODES; base += 1024) {
        int i = base + threadIdx.x;
        int v = (i < N_NODES) ? g_counts[i] : 0;
        int incl = v;
        #pragma unroll
        for (int o = 1; o < 32; o <<= 1) {
            int t = __shfl_up_sync(0xffffffffu, incl, o);
            if (lane >= o) incl += t;
        }
        if (lane == 31) warpsum[w] = incl;
        __syncthreads();
        if (w == 0) {
            int s = warpsum[lane];
            #pragma unroll
            for (int o = 1; o < 32; o <<= 1) {
                int t = __shfl_up_sync(0xffffffffu, s, o);
                if (lane >= o) s += t;
            }
            warpsum[lane] = s;
        }
        __syncthreads();
        int woff = (w > 0) ? warpsum[w - 1] : 0;
        if (i < N_NODES) g_rowstart[i] = carry + woff + incl - v;
        int total = warpsum[31];
        __syncthreads();
        carry += total;
    }
    if (threadIdx.x == 0) g_rowstart[N_NODES] = carry;
}

__global__ void setup_kernel() {
    int i = blockIdx.x * blockDim.x + threadIdx.x;
    if (i < N_NODES) {
        g_dinv[i]   = rsqrtf((float)(g_counts[i] + 1));  // +1 self-loop
        g_cursor[i] = g_rowstart[i];
    }
}

__global__ void scatter_kernel(const int* __restrict__ srcp,
                               const int* __restrict__ dstp) {
    int e = blockIdx.x * blockDim.x + threadIdx.x;
    if (e < N_EDGES) {
        int d = dstp[e];
        int pos = atomicAdd(&g_cursor[d], 1);
        g_srcsorted[pos] = srcp[e];
    }
}

// ---------------- GEMM: out = dinv ⊙ (A @ W), M=50000, N=K=256 ------------
#define BM 128
#define BN 128
#define BK 8

// LAYER==1: A = x (param), LAYER==2: A = h_buf.  Output always g_buf.
template <int LAYER>
__global__ __launch_bounds__(256) void gemm_scale_kernel(
        const float* __restrict__ Ain, const float* __restrict__ W) {
    __shared__ float As[2][BK][BM];
    __shared__ float Bs[2][BK][BN];

    const float* __restrict__ A = (LAYER == 1) ? Ain : (const float*)h_buf;
    float* __restrict__ C = g_buf;

    const int tid     = threadIdx.x;
    const int rowBase = blockIdx.x * BM;
    const int colBase = blockIdx.y * BN;
    const int tx = tid & 15;          // 0..15 (col group)
    const int ty = tid >> 4;          // 0..15 (row group)
    const int aRow = tid >> 1;        // 0..127
    const int aCol = (tid & 1) * 4;   // 0 or 4
    const int wRow = tid >> 5;        // 0..7
    const int wCol = (tid & 31) * 4;  // 0..124

    float acc[8][8];
    #pragma unroll
    for (int i = 0; i < 8; i++)
        #pragma unroll
        for (int j = 0; j < 8; j++) acc[i][j] = 0.f;

    // prologue: tile 0
    {
        float4 av = make_float4(0.f, 0.f, 0.f, 0.f);
        int gr = rowBase + aRow;
        if (gr < N_NODES) av = *(const float4*)&A[gr * F + aCol];
        As[0][aCol + 0][aRow] = av.x;
        As[0][aCol + 1][aRow] = av.y;
        As[0][aCol + 2][aRow] = av.z;
        As[0][aCol + 3][aRow] = av.w;
        float4 wv = *(const float4*)&W[wRow * F + colBase + wCol];
        *(float4*)&Bs[0][wRow][wCol] = wv;
    }
    __syncthreads();

    int buf = 0;
    #pragma unroll 4
    for (int kt = 0; kt < F / BK; ++kt) {
        const int knext = (kt + 1) * BK;
        float4 av = make_float4(0.f, 0.f, 0.f, 0.f);
        float4 wv = make_float4(0.f, 0.f, 0.f, 0.f);
        if (knext < F) {
            int gr = rowBase + aRow;
            if (gr < N_NODES) av = *(const float4*)&A[gr * F + knext + aCol];
            wv = *(const float4*)&W[(knext + wRow) * F + colBase + wCol];
        }
        // compute on current buffer
        #pragma unroll
        for (int kk = 0; kk < BK; ++kk) {
            float ra[8], rb[8];
            #pragma unroll
            for (int i = 0; i < 8; i++) ra[i] = As[buf][kk][ty * 8 + i];
            #pragma unroll
            for (int j = 0; j < 8; j++) rb[j] = Bs[buf][kk][tx * 8 + j];
            #pragma unroll
            for (int i = 0; i < 8; i++)
                #pragma unroll
                for (int j = 0; j < 8; j++) acc[i][j] += ra[i] * rb[j];
        }
        if (knext < F) {
            As[buf ^ 1][aCol + 0][aRow] = av.x;
            As[buf ^ 1][aCol + 1][aRow] = av.y;
            As[buf ^ 1][aCol + 2][aRow] = av.z;
            As[buf ^ 1][aCol + 3][aRow] = av.w;
            *(float4*)&Bs[buf ^ 1][wRow][wCol] = wv;
        }
        __syncthreads();
        buf ^= 1;
    }

    // epilogue: scale rows by dinv and store
    #pragma unroll
    for (int i = 0; i < 8; i++) {
        int r = rowBase + ty * 8 + i;
        if (r < N_NODES) {
            float s = g_dinv[r];
            #pragma unroll
            for (int j = 0; j < 8; j += 4) {
                float4 v;
                v.x = s * acc[i][j + 0];
                v.y = s * acc[i][j + 1];
                v.z = s * acc[i][j + 2];
                v.w = s * acc[i][j + 3];
                *(float4*)&C[r * F + colBase + tx * 8 + j] = v;
            }
        }
    }
}

// ---------------- SpMM (CSR row-sum) + bias + ReLU (+ residual) -----------
// FINAL==0: h_buf[d] = relu(dinv[d]*(g[d] + sum g[src]) + b)
// FINAL==1: out[d]   = 0.5*(x[d] + relu(dinv[d]*(g[d] + sum g[src]) + b))
template <bool FINAL>
__global__ __launch_bounds__(256) void spmm_kernel(
        const float* __restrict__ bias,
        const float* __restrict__ xres,
        float* __restrict__ outp) {
    const int d = blockIdx.x;
    const int c = threadIdx.x;
    const float* __restrict__ g = g_buf;

    const int s = g_rowstart[d];
    const int e = g_rowstart[d + 1];

    float acc = g[d * F + c];  // self-loop term
    int j = s;
    for (; j + 4 <= e; j += 4) {
        int i0 = g_srcsorted[j + 0];
        int i1 = g_srcsorted[j + 1];
        int i2 = g_srcsorted[j + 2];
        int i3 = g_srcsorted[j + 3];
        float v0 = g[i0 * F + c];
        float v1 = g[i1 * F + c];
        float v2 = g[i2 * F + c];
        float v3 = g[i3 * F + c];
        acc += v0 + v1 + v2 + v3;
    }
    for (; j < e; ++j) acc += g[g_srcsorted[j] * F + c];

    float v = fmaxf(g_dinv[d] * acc + bias[c], 0.f);
    if (FINAL) {
        outp[d * F + c] = 0.5f * (xres[d * F + c] + v);
    } else {
        h_buf[d * F + c] = v;
    }
}

// ---------------- launch ---------------------------------------------------
extern "C" void kernel_launch(void* const* d_in, const int* in_sizes, int n_in,
                              void* d_out, int out_size) {
    const float* x  = (const float*)d_in[0];
    const int*   ei = (const int*)d_in[1];
    const float* W1 = (const float*)d_in[2];
    const float* b1 = (const float*)d_in[3];
    const float* W2 = (const float*)d_in[4];
    const float* b2 = (const float*)d_in[5];
    float* out = (float*)d_out;

    const int* srcp = ei;             // edge_index[0]
    const int* dstp = ei + N_EDGES;   // edge_index[1]

    const int TB = 256;
    init_counts_kernel<<<(N_NODES + TB - 1) / TB, TB>>>();
    hist_kernel<<<(N_EDGES + TB - 1) / TB, TB>>>(dstp);
    scan_kernel<<<1, 1024>>>();
    setup_kernel<<<(N_NODES + TB - 1) / TB, TB>>>();
    scatter_kernel<<<(N_EDGES + TB - 1) / TB, TB>>>(srcp, dstp);

    dim3 gemm_grid((N_NODES + BM - 1) / BM, F / BN);
    gemm_scale_kernel<1><<<gemm_grid, 256>>>(x, W1);
    spmm_kernel<false><<<N_NODES, 256>>>(b1, nullptr, nullptr);
    gemm_scale_kernel<2><<<gemm_grid, 256>>>(nullptr, W2);
    spmm_kernel<true><<<N_NODES, 256>>>(b2, x, out);
}

// round 2
// speedup vs baseline: 1.2454x; 1.2454x over previous
#include <cuda_runtime.h>

#define N_NODES 50000
#define N_EDGES 800000
#define F 256

// ---------------- scratch (static device globals; no runtime alloc) -------
__device__ float g_buf[(size_t)N_NODES * F];   // dinv-scaled GEMM output
__device__ float h_buf[(size_t)N_NODES * F];   // layer-1 activations
__device__ int   g_counts[N_NODES];
__device__ int   g_rowstart[N_NODES + 1];
__device__ int   g_cursor[N_NODES];
__device__ float g_dinv[N_NODES];
__device__ int   g_srcsorted[N_EDGES];

// ---------------- graph preprocessing -------------------------------------
__global__ void init_counts_kernel() {
    int i = blockIdx.x * blockDim.x + threadIdx.x;
    if (i < N_NODES) g_counts[i] = 0;
}

__global__ void hist_kernel(const int* __restrict__ dstp) {
    int e = blockIdx.x * blockDim.x + threadIdx.x;
    if (e < N_EDGES) atomicAdd(&g_counts[dstp[e]], 1);
}

// single-block exclusive scan of g_counts -> g_rowstart (50k elements)
__global__ void scan_kernel() {
    __shared__ int warpsum[32];
    const int lane = threadIdx.x & 31;
    const int w    = threadIdx.x >> 5;
    int carry = 0;
    for (int base = 0; base < N_NODES; base += 1024) {
        int i = base + threadIdx.x;
        int v = (i < N_NODES) ? g_counts[i] : 0;
        int incl = v;
        #pragma unroll
        for (int o = 1; o < 32; o <<= 1) {
            int t = __shfl_up_sync(0xffffffffu, incl, o);
            if (lane >= o) incl += t;
        }
        if (lane == 31) warpsum[w] = incl;
        __syncthreads();
        if (w == 0) {
            int s = warpsum[lane];
            #pragma unroll
            for (int o = 1; o < 32; o <<= 1) {
                int t = __shfl_up_sync(0xffffffffu, s, o);
                if (lane >= o) s += t;
            }
            warpsum[lane] = s;
        }
        __syncthreads();
        int woff = (w > 0) ? warpsum[w - 1] : 0;
        if (i < N_NODES) g_rowstart[i] = carry + woff + incl - v;
        int total = warpsum[31];
        __syncthreads();
        carry += total;
    }
    if (threadIdx.x == 0) g_rowstart[N_NODES] = carry;
}

__global__ void setup_kernel() {
    int i = blockIdx.x * blockDim.x + threadIdx.x;
    if (i < N_NODES) {
        g_dinv[i]   = rsqrtf((float)(g_counts[i] + 1));  // +1 self-loop
        g_cursor[i] = g_rowstart[i];
    }
}

__global__ void scatter_kernel(const int* __restrict__ srcp,
                               const int* __restrict__ dstp) {
    int e = blockIdx.x * blockDim.x + threadIdx.x;
    if (e < N_EDGES) {
        int d = dstp[e];
        int pos = atomicAdd(&g_cursor[d], 1);
        g_srcsorted[pos] = srcp[e];
    }
}

// ---------------- tf32 helpers ---------------------------------------------
__device__ __forceinline__ float f2tf32(float x) {
    unsigned r;
    asm("cvt.rna.tf32.f32 %0, %1;" : "=r"(r) : "f"(x));
    return __uint_as_float(r);
}

__device__ __forceinline__ void mma_tf32(float* c, const unsigned* a, const unsigned* b) {
    asm volatile(
        "mma.sync.aligned.m16n8k8.row.col.f32.tf32.tf32.f32 "
        "{%0,%1,%2,%3}, {%4,%5,%6,%7}, {%8,%9}, {%0,%1,%2,%3};\n"
        : "+f"(c[0]), "+f"(c[1]), "+f"(c[2]), "+f"(c[3])
        : "r"(a[0]), "r"(a[1]), "r"(a[2]), "r"(a[3]), "r"(b[0]), "r"(b[1]));
}

// ---------------- GEMM (tf32 tensor cores): out = dinv ⊙ (A @ W) ----------
// M=50000, N=K=256. Block tile 128x128xBK(=8). 8 warps: 2(M) x 4(N),
// warp tile 64x32 -> 4x4 grid of m16n8k8 MMAs per k-step.
#define BM 128
#define BN 128
#define BK 8
#define APAD 132   // 128 + 4 pad -> conflict-free fragment LDS

template <int LAYER>
__global__ __launch_bounds__(256) void gemm_tc_kernel(
        const float* __restrict__ Ain, const float* __restrict__ W) {
    __shared__ float As[2][BK][APAD];  // [k][row]
    __shared__ float Bs[2][BK][APAD];  // [k][col]

    const float* __restrict__ A = (LAYER == 1) ? Ain : (const float*)h_buf;
    float* __restrict__ C = g_buf;

    const int tid     = threadIdx.x;
    const int lane    = tid & 31;
    const int warp    = tid >> 5;
    const int warpM   = warp & 1;     // 0..1 -> 64-row slab
    const int warpN   = warp >> 1;    // 0..3 -> 32-col slab
    const int rowBase = blockIdx.x * BM;
    const int colBase = blockIdx.y * BN;

    const int aRow = tid >> 1;        // 0..127
    const int aCol = (tid & 1) * 4;   // 0 or 4
    const int wRow = tid >> 5;        // 0..7   (k row of W tile)
    const int wCol = (tid & 31) * 4;  // 0..124

    float acc[4][4][4];
    #pragma unroll
    for (int mi = 0; mi < 4; mi++)
        #pragma unroll
        for (int ni = 0; ni < 4; ni++)
            #pragma unroll
            for (int q = 0; q < 4; q++) acc[mi][ni][q] = 0.f;

    // prologue: tile 0
    {
        float4 av = make_float4(0.f, 0.f, 0.f, 0.f);
        int gr = rowBase + aRow;
        if (gr < N_NODES) av = *(const float4*)&A[gr * F + aCol];
        As[0][aCol + 0][aRow] = f2tf32(av.x);
        As[0][aCol + 1][aRow] = f2tf32(av.y);
        As[0][aCol + 2][aRow] = f2tf32(av.z);
        As[0][aCol + 3][aRow] = f2tf32(av.w);
        float4 wv = *(const float4*)&W[wRow * F + colBase + wCol];
        float4 wt;
        wt.x = f2tf32(wv.x); wt.y = f2tf32(wv.y);
        wt.z = f2tf32(wv.z); wt.w = f2tf32(wv.w);
        *(float4*)&Bs[0][wRow][wCol] = wt;
    }
    __syncthreads();

    int buf = 0;
    #pragma unroll 4
    for (int kt = 0; kt < F / BK; ++kt) {
        const int knext = (kt + 1) * BK;
        float4 av = make_float4(0.f, 0.f, 0.f, 0.f);
        float4 wv = make_float4(0.f, 0.f, 0.f, 0.f);
        if (knext < F) {
            int gr = rowBase + aRow;
            if (gr < N_NODES) av = *(const float4*)&A[gr * F + knext + aCol];
            wv = *(const float4*)&W[(knext + wRow) * F + colBase + wCol];
        }

        // ---- fragment loads ----
        unsigned afr[4][4], bfr[4][2];
        const int kq = lane & 3;
        const int rq = lane >> 2;
        #pragma unroll
        for (int mi = 0; mi < 4; mi++) {
            int r = warpM * 64 + mi * 16 + rq;
            afr[mi][0] = __float_as_uint(As[buf][kq    ][r]);
            afr[mi][1] = __float_as_uint(As[buf][kq    ][r + 8]);
            afr[mi][2] = __float_as_uint(As[buf][kq + 4][r]);
            afr[mi][3] = __float_as_uint(As[buf][kq + 4][r + 8]);
        }
        #pragma unroll
        for (int ni = 0; ni < 4; ni++) {
            int c = warpN * 32 + ni * 8 + rq;
            bfr[ni][0] = __float_as_uint(Bs[buf][kq    ][c]);
            bfr[ni][1] = __float_as_uint(Bs[buf][kq + 4][c]);
        }
        #pragma unroll
        for (int mi = 0; mi < 4; mi++)
            #pragma unroll
            for (int ni = 0; ni < 4; ni++)
                mma_tf32(acc[mi][ni], afr[mi], bfr[ni]);

        if (knext < F) {
            As[buf ^ 1][aCol + 0][aRow] = f2tf32(av.x);
            As[buf ^ 1][aCol + 1][aRow] = f2tf32(av.y);
            As[buf ^ 1][aCol + 2][aRow] = f2tf32(av.z);
            As[buf ^ 1][aCol + 3][aRow] = f2tf32(av.w);
            float4 wt;
            wt.x = f2tf32(wv.x); wt.y = f2tf32(wv.y);
            wt.z = f2tf32(wv.z); wt.w = f2tf32(wv.w);
            *(float4*)&Bs[buf ^ 1][wRow][wCol] = wt;
        }
        __syncthreads();
        buf ^= 1;
    }

    // epilogue: scale rows by dinv, store float2 per fragment pair
    const int kq = lane & 3;
    const int rq = lane >> 2;
    #pragma unroll
    for (int mi = 0; mi < 4; mi++) {
        int r0 = rowBase + warpM * 64 + mi * 16 + rq;
        int r1 = r0 + 8;
        float s0 = (r0 < N_NODES) ? g_dinv[r0] : 0.f;
        float s1 = (r1 < N_NODES) ? g_dinv[r1] : 0.f;
        #pragma unroll
        for (int ni = 0; ni < 4; ni++) {
            int c = colBase + warpN * 32 + ni * 8 + 2 * kq;
            if (r0 < N_NODES) {
                float2 v0 = make_float2(s0 * acc[mi][ni][0], s0 * acc[mi][ni][1]);
                *(float2*)&C[r0 * F + c] = v0;
            }
            if (r1 < N_NODES) {
                float2 v1 = make_float2(s1 * acc[mi][ni][2], s1 * acc[mi][ni][3]);
                *(float2*)&C[r1 * F + c] = v1;
            }
        }
    }
}

// ---------------- SpMM (CSR row-sum) + bias + ReLU (+ residual) -----------
template <bool FINAL>
__global__ __launch_bounds__(256) void spmm_kernel(
        const float* __restrict__ bias,
        const float* __restrict__ xres,
        float* __restrict__ outp) {
    const int d = blockIdx.x;
    const int c = threadIdx.x;
    const float* __restrict__ g = g_buf;

    const int s = g_rowstart[d];
    const int e = g_rowstart[d + 1];

    float acc = g[d * F + c];  // self-loop term
    int j = s;
    for (; j + 4 <= e; j += 4) {
        int i0 = g_srcsorted[j + 0];
        int i1 = g_srcsorted[j + 1];
        int i2 = g_srcsorted[j + 2];
        int i3 = g_srcsorted[j + 3];
        float v0 = g[i0 * F + c];
        float v1 = g[i1 * F + c];
        float v2 = g[i2 * F + c];
        float v3 = g[i3 * F + c];
        acc += v0 + v1 + v2 + v3;
    }
    for (; j < e; ++j) acc += g[g_srcsorted[j] * F + c];

    float v = fmaxf(g_dinv[d] * acc + bias[c], 0.f);
    if (FINAL) {
        outp[d * F + c] = 0.5f * (xres[d * F + c] + v);
    } else {
        h_buf[d * F + c] = v;
    }
}

// ---------------- launch ---------------------------------------------------
extern "C" void kernel_launch(void* const* d_in, const int* in_sizes, int n_in,
                              void* d_out, int out_size) {
    const float* x  = (const float*)d_in[0];
    const int*   ei = (const int*)d_in[1];
    const float* W1 = (const float*)d_in[2];
    const float* b1 = (const float*)d_in[3];
    const float* W2 = (const float*)d_in[4];
    const float* b2 = (const float*)d_in[5];
    float* out = (float*)d_out;

    const int* srcp = ei;             // edge_index[0]
    const int* dstp = ei + N_EDGES;   // edge_index[1]

    const int TB = 256;
    init_counts_kernel<<<(N_NODES + TB - 1) / TB, TB>>>();
    hist_kernel<<<(N_EDGES + TB - 1) / TB, TB>>>(dstp);
    scan_kernel<<<1, 1024>>>();
    setup_kernel<<<(N_NODES + TB - 1) / TB, TB>>>();
    scatter_kernel<<<(N_EDGES + TB - 1) / TB, TB>>>(srcp, dstp);

    dim3 gemm_grid((N_NODES + BM - 1) / BM, F / BN);
    gemm_tc_kernel<1><<<gemm_grid, 256>>>(x, W1);
    spmm_kernel<false><<<N_NODES, 256>>>(b1, nullptr, nullptr);
    gemm_tc_kernel<2><<<gemm_grid, 256>>>(nullptr, W2);
    spmm_kernel<true><<<N_NODES, 256>>>(b2, x, out);
}

// round 5
// speedup vs baseline: 1.4982x; 1.2030x over previous
#include <cuda_runtime.h>
#include <cuda_bf16.h>

#define N_NODES 50000
#define N_EDGES 800000
#define F 256

// ---------------- scratch (static device globals; no runtime alloc) -------
__device__ float g_buf[(size_t)N_NODES * F];   // dinv-scaled GEMM output
__device__ float h_buf[(size_t)N_NODES * F];   // layer-1 activations
__device__ int   g_counts[N_NODES];
__device__ int   g_rowstart[N_NODES + 1];
__device__ int   g_cursor[N_NODES];
__device__ float g_dinv[N_NODES];
__device__ int   g_srcsorted[N_EDGES];

// ---------------- graph preprocessing -------------------------------------
__global__ void init_counts_kernel() {
    int i = blockIdx.x * blockDim.x + threadIdx.x;
    if (i < N_NODES) g_counts[i] = 0;
}

__global__ void hist_kernel(const int* __restrict__ dstp) {
    int e = blockIdx.x * blockDim.x + threadIdx.x;
    if (e < N_EDGES) atomicAdd(&g_counts[dstp[e]], 1);
}

// single-block exclusive scan of g_counts -> g_rowstart (50k elements)
__global__ void scan_kernel() {
    __shared__ int warpsum[32];
    const int lane = threadIdx.x & 31;
    const int w    = threadIdx.x >> 5;
    int carry = 0;
    for (int base = 0; base < N_NODES; base += 1024) {
        int i = base + threadIdx.x;
        int v = (i < N_NODES) ? g_counts[i] : 0;
        int incl = v;
        #pragma unroll
        for (int o = 1; o < 32; o <<= 1) {
            int t = __shfl_up_sync(0xffffffffu, incl, o);
            if (lane >= o) incl += t;
        }
        if (lane == 31) warpsum[w] = incl;
        __syncthreads();
        if (w == 0) {
            int s = warpsum[lane];
            #pragma unroll
            for (int o = 1; o < 32; o <<= 1) {
                int t = __shfl_up_sync(0xffffffffu, s, o);
                if (lane >= o) s += t;
            }
            warpsum[lane] = s;
        }
        __syncthreads();
        int woff = (w > 0) ? warpsum[w - 1] : 0;
        if (i < N_NODES) g_rowstart[i] = carry + woff + incl - v;
        int total = warpsum[31];
        __syncthreads();
        carry += total;
    }
    if (threadIdx.x == 0) g_rowstart[N_NODES] = carry;
}

__global__ void setup_kernel() {
    int i = blockIdx.x * blockDim.x + threadIdx.x;
    if (i < N_NODES) {
        g_dinv[i]   = rsqrtf((float)(g_counts[i] + 1));  // +1 self-loop
        g_cursor[i] = g_rowstart[i];
    }
}

__global__ void scatter_kernel(const int* __restrict__ srcp,
                               const int* __restrict__ dstp) {
    int e = blockIdx.x * blockDim.x + threadIdx.x;
    if (e < N_EDGES) {
        int d = dstp[e];
        int pos = atomicAdd(&g_cursor[d], 1);
        g_srcsorted[pos] = srcp[e];
    }
}

// ---------------- bf16 helpers ---------------------------------------------
__device__ __forceinline__ unsigned pack_bf16(float a, float b) {
    __nv_bfloat162 t = __floats2bfloat162_rn(a, b);
    return *(unsigned*)&t;
}

__device__ __forceinline__ void ldsm_x4(unsigned& r0, unsigned& r1,
                                        unsigned& r2, unsigned& r3,
                                        unsigned addr) {
    asm volatile("ldmatrix.sync.aligned.m8n8.x4.shared.b16 {%0,%1,%2,%3}, [%4];"
                 : "=r"(r0), "=r"(r1), "=r"(r2), "=r"(r3) : "r"(addr));
}

__device__ __forceinline__ void ldsm_x4_t(unsigned& r0, unsigned& r1,
                                          unsigned& r2, unsigned& r3,
                                          unsigned addr) {
    asm volatile("ldmatrix.sync.aligned.m8n8.x4.trans.shared.b16 {%0,%1,%2,%3}, [%4];"
                 : "=r"(r0), "=r"(r1), "=r"(r2), "=r"(r3) : "r"(addr));
}

__device__ __forceinline__ void mma_bf16(float* c, const unsigned* a,
                                         unsigned b0, unsigned b1) {
    asm volatile(
        "mma.sync.aligned.m16n8k16.row.col.f32.bf16.bf16.f32 "
        "{%0,%1,%2,%3}, {%4,%5,%6,%7}, {%8,%9}, {%0,%1,%2,%3};\n"
        : "+f"(c[0]), "+f"(c[1]), "+f"(c[2]), "+f"(c[3])
        : "r"(a[0]), "r"(a[1]), "r"(a[2]), "r"(a[3]), "r"(b0), "r"(b1));
}

// ---------------- GEMM (bf16 tensor cores): out = dinv ⊙ (A @ W) ----------
// M=50000, N=K=256. Block 128x128xBK(=16). 8 warps 2(M)x4(N), warp 64x32.
// Per k-tile per warp: 4 ldmatrix.x4 (A) + 2 ldmatrix.x4.trans (B) feed 16 MMAs.
#define BM 128
#define BN 128
#define BK 16
#define APITCH 24   // ushorts: 48B rows -> 3r mod 8 bijective (LDSM conflict-free)
#define BPITCH 136  // ushorts: 272B rows -> 17r mod 8 = r (conflict-free)

template <int LAYER>
__global__ __launch_bounds__(256) void gemm_bf16_kernel(
        const float* __restrict__ Ain, const float* __restrict__ W) {
    __shared__ __align__(16) unsigned short As[2][BM * APITCH];
    __shared__ __align__(16) unsigned short Bs[2][BK * BPITCH];

    const float* __restrict__ A = (LAYER == 1) ? Ain : (const float*)h_buf;
    float* __restrict__ C = g_buf;

    const int tid   = threadIdx.x;
    const int lane  = tid & 31;
    const int warp  = tid >> 5;
    const int warpM = warp & 1;    // 64-row slab
    const int warpN = warp >> 1;   // 32-col slab
    const int rowBase = blockIdx.x * BM;
    const int colBase = blockIdx.y * BN;

    // A staging: thread -> row (tid>>1), k-half (tid&1)*8 (8 floats = 2 float4)
    const int aRow = tid >> 1;
    const int aK   = (tid & 1) * 8;
    const int gr   = rowBase + aRow;
    const bool aOk = (gr < N_NODES);
    // B staging: thread -> k-row (tid>>4), n-offset (tid&15)*8 (8 floats)
    const int bK = tid >> 4;
    const int bN = (tid & 15) * 8;

    float acc[4][4][4];
    #pragma unroll
    for (int mi = 0; mi < 4; mi++)
        #pragma unroll
        for (int ni = 0; ni < 4; ni++)
            #pragma unroll
            for (int q = 0; q < 4; q++) acc[mi][ni][q] = 0.f;

    // ---- prologue: stage tile 0 ----
    {
        float4 a0 = make_float4(0.f,0.f,0.f,0.f), a1 = a0;
        if (aOk) {
            a0 = *(const float4*)&A[(size_t)gr * F + aK];
            a1 = *(const float4*)&A[(size_t)gr * F + aK + 4];
        }
        uint4 av;
        av.x = pack_bf16(a0.x, a0.y); av.y = pack_bf16(a0.z, a0.w);
        av.z = pack_bf16(a1.x, a1.y); av.w = pack_bf16(a1.z, a1.w);
        *(uint4*)&As[0][aRow * APITCH + aK] = av;

        float4 b0 = *(const float4*)&W[(size_t)bK * F + colBase + bN];
        float4 b1 = *(const float4*)&W[(size_t)bK * F + colBase + bN + 4];
        uint4 bv;
        bv.x = pack_bf16(b0.x, b0.y); bv.y = pack_bf16(b0.z, b0.w);
        bv.z = pack_bf16(b1.x, b1.y); bv.w = pack_bf16(b1.z, b1.w);
        *(uint4*)&Bs[0][bK * BPITCH + bN] = bv;
    }
    __syncthreads();

    // fragment smem addresses (32-bit shared space)
    const unsigned asBase = (unsigned)__cvta_generic_to_shared(&As[0][0]);
    const unsigned bsBase = (unsigned)__cvta_generic_to_shared(&Bs[0][0]);
    const unsigned asBuf  = BM * APITCH * 2;  // bytes per A buffer
    const unsigned bsBuf  = BK * BPITCH * 2;
    // A frag: row = warpM*64 + mi*16 + (lane&15), k-col = (lane>>4)*8
    const unsigned aFragOff =
        (unsigned)((warpM * 64 + (lane & 15)) * APITCH + (lane >> 4) * 8) * 2;
    // B frag: k = lane&15, n = warpN*32 + nb*16 + (lane>>4)*8
    const unsigned bFragOff =
        (unsigned)((lane & 15) * BPITCH + warpN * 32 + (lane >> 4) * 8) * 2;

    int buf = 0;
    #pragma unroll 2
    for (int kt = 0; kt < F / BK; ++kt) {
        const int knext = (kt + 1) * BK;
        float4 a0, a1, b0, b1;
        if (knext < F) {
            a0 = make_float4(0.f,0.f,0.f,0.f); a1 = a0;
            if (aOk) {
                a0 = *(const float4*)&A[(size_t)gr * F + knext + aK];
                a1 = *(const float4*)&A[(size_t)gr * F + knext + aK + 4];
            }
            b0 = *(const float4*)&W[(size_t)(knext + bK) * F + colBase + bN];
            b1 = *(const float4*)&W[(size_t)(knext + bK) * F + colBase + bN + 4];
        }

        // ---- fragment loads via ldmatrix ----
        unsigned afr[4][4], bfr[2][4];
        #pragma unroll
        for (int mi = 0; mi < 4; mi++)
            ldsm_x4(afr[mi][0], afr[mi][1], afr[mi][2], afr[mi][3],
                    asBase + buf * asBuf + aFragOff + (unsigned)(mi * 16 * APITCH * 2));
        #pragma unroll
        for (int nb = 0; nb < 2; nb++)
            ldsm_x4_t(bfr[nb][0], bfr[nb][1], bfr[nb][2], bfr[nb][3],
                      bsBase + buf * bsBuf + bFragOff + (unsigned)(nb * 16 * 2));

        #pragma unroll
        for (int mi = 0; mi < 4; mi++)
            #pragma unroll
            for (int ni = 0; ni < 4; ni++)
                mma_bf16(acc[mi][ni], afr[mi],
                         bfr[ni >> 1][(ni & 1) * 2], bfr[ni >> 1][(ni & 1) * 2 + 1]);

        if (knext < F) {
            uint4 av;
            av.x = pack_bf16(a0.x, a0.y); av.y = pack_bf16(a0.z, a0.w);
            av.z = pack_bf16(a1.x, a1.y); av.w = pack_bf16(a1.z, a1.w);
            *(uint4*)&As[buf ^ 1][aRow * APITCH + aK] = av;
            uint4 bv;
            bv.x = pack_bf16(b0.x, b0.y); bv.y = pack_bf16(b0.z, b0.w);
            bv.z = pack_bf16(b1.x, b1.y); bv.w = pack_bf16(b1.z, b1.w);
            *(uint4*)&Bs[buf ^ 1][bK * BPITCH + bN] = bv;
        }
        __syncthreads();
        buf ^= 1;
    }

    // ---- epilogue: scale rows by dinv, store float2 per fragment pair ----
    const int g  = lane >> 2;
    const int tg = lane & 3;
    #pragma unroll
    for (int mi = 0; mi < 4; mi++) {
        int r0 = rowBase + warpM * 64 + mi * 16 + g;
        int r1 = r0 + 8;
        float s0 = (r0 < N_NODES) ? g_dinv[r0] : 0.f;
        float s1 = (r1 < N_NODES) ? g_dinv[r1] : 0.f;
        #pragma unroll
        for (int ni = 0; ni < 4; ni++) {
            int c = colBase + warpN * 32 + ni * 8 + 2 * tg;
            if (r0 < N_NODES)
                *(float2*)&C[(size_t)r0 * F + c] =
                    make_float2(s0 * acc[mi][ni][0], s0 * acc[mi][ni][1]);
            if (r1 < N_NODES)
                *(float2*)&C[(size_t)r1 * F + c] =
                    make_float2(s1 * acc[mi][ni][2], s1 * acc[mi][ni][3]);
        }
    }
}

// ---------------- SpMM (CSR row-sum) + bias + ReLU (+ residual) -----------
template <bool FINAL>
__global__ __launch_bounds__(256) void spmm_kernel(
        const float* __restrict__ bias,
        const float* __restrict__ xres,
        float* __restrict__ outp) {
    const int d = blockIdx.x;
    const int c = threadIdx.x;
    const float* __restrict__ g = g_buf;

    const int s = g_rowstart[d];
    const int e = g_rowstart[d + 1];

    float acc = g[(size_t)d * F + c];  // self-loop term
    int j = s;
    for (; j + 4 <= e; j += 4) {
        int i0 = g_srcsorted[j + 0];
        int i1 = g_srcsorted[j + 1];
        int i2 = g_srcsorted[j + 2];
        int i3 = g_srcsorted[j + 3];
        float v0 = g[(size_t)i0 * F + c];
        float v1 = g[(size_t)i1 * F + c];
        float v2 = g[(size_t)i2 * F + c];
        float v3 = g[(size_t)i3 * F + c];
        acc += v0 + v1 + v2 + v3;
    }
    for (; j < e; ++j) acc += g[(size_t)g_srcsorted[j] * F + c];

    float v = fmaxf(g_dinv[d] * acc + bias[c], 0.f);
    if (FINAL) {
        outp[(size_t)d * F + c] = 0.5f * (xres[(size_t)d * F + c] + v);
    } else {
        h_buf[(size_t)d * F + c] = v;
    }
}

// ---------------- launch ---------------------------------------------------
extern "C" void kernel_launch(void* const* d_in, const int* in_sizes, int n_in,
                              void* d_out, int out_size) {
    const float* x  = (const float*)d_in[0];
    const int*   ei = (const int*)d_in[1];
    const float* W1 = (const float*)d_in[2];
    const float* b1 = (const float*)d_in[3];
    const float* W2 = (const float*)d_in[4];
    const float* b2 = (const float*)d_in[5];
    float* out = (float*)d_out;

    const int* srcp = ei;             // edge_index[0]
    const int* dstp = ei + N_EDGES;   // edge_index[1]

    const int TB = 256;
    init_counts_kernel<<<(N_NODES + TB - 1) / TB, TB>>>();
    hist_kernel<<<(N_EDGES + TB - 1) / TB, TB>>>(dstp);
    scan_kernel<<<1, 1024>>>();
    setup_kernel<<<(N_NODES + TB - 1) / TB, TB>>>();
    scatter_kernel<<<(N_EDGES + TB - 1) / TB, TB>>>(srcp, dstp);

    dim3 gemm_grid((N_NODES + BM - 1) / BM, F / BN);
    gemm_bf16_kernel<1><<<gemm_grid, 256>>>(x, W1);
    spmm_kernel<false><<<N_NODES, 256>>>(b1, nullptr, nullptr);
    gemm_bf16_kernel<2><<<gemm_grid, 256>>>(nullptr, W2);
    spmm_kernel<true><<<N_NODES, 256>>>(b2, x, out);
}

// round 6
// speedup vs baseline: 2.1709x; 1.4490x over previous
#include <cuda_runtime.h>
#include <cuda_bf16.h>

#define N_NODES 50000
#define N_EDGES 800000
#define F 256
#define F2 (F / 2)

// ---------------- scratch (static device globals; no runtime alloc) -------
// g/h buffers hold bf16x2 packed per u32 (row-major, F2 words per row)
__device__ __align__(16) unsigned g_buf16[(size_t)N_NODES * F2];
__device__ __align__(16) unsigned h_buf16[(size_t)N_NODES * F2];
__device__ int   g_counts[N_NODES];
__device__ int   g_rowstart[N_NODES + 1];
__device__ int   g_cursor[N_NODES];
__device__ float g_dinv[N_NODES];
__device__ int   g_srcsorted[N_EDGES];

// ---------------- graph preprocessing -------------------------------------
__global__ void init_counts_kernel() {
    int i = blockIdx.x * blockDim.x + threadIdx.x;
    if (i < N_NODES) g_counts[i] = 0;
}

__global__ void hist_kernel(const int* __restrict__ dstp) {
    int e = blockIdx.x * blockDim.x + threadIdx.x;
    if (e < N_EDGES) atomicAdd(&g_counts[dstp[e]], 1);
}

// single-block exclusive scan of g_counts -> g_rowstart (50k elements)
__global__ void scan_kernel() {
    __shared__ int warpsum[32];
    const int lane = threadIdx.x & 31;
    const int w    = threadIdx.x >> 5;
    int carry = 0;
    for (int base = 0; base < N_NODES; base += 1024) {
        int i = base + threadIdx.x;
        int v = (i < N_NODES) ? g_counts[i] : 0;
        int incl = v;
        #pragma unroll
        for (int o = 1; o < 32; o <<= 1) {
            int t = __shfl_up_sync(0xffffffffu, incl, o);
            if (lane >= o) incl += t;
        }
        if (lane == 31) warpsum[w] = incl;
        __syncthreads();
        if (w == 0) {
            int s = warpsum[lane];
            #pragma unroll
            for (int o = 1; o < 32; o <<= 1) {
                int t = __shfl_up_sync(0xffffffffu, s, o);
                if (lane >= o) s += t;
            }
            warpsum[lane] = s;
        }
        __syncthreads();
        int woff = (w > 0) ? warpsum[w - 1] : 0;
        if (i < N_NODES) g_rowstart[i] = carry + woff + incl - v;
        int total = warpsum[31];
        __syncthreads();
        carry += total;
    }
    if (threadIdx.x == 0) g_rowstart[N_NODES] = carry;
}

__global__ void setup_kernel() {
    int i = blockIdx.x * blockDim.x + threadIdx.x;
    if (i < N_NODES) {
        g_dinv[i]   = rsqrtf((float)(g_counts[i] + 1));  // +1 self-loop
        g_cursor[i] = g_rowstart[i];
    }
}

__global__ void scatter_kernel(const int* __restrict__ srcp,
                               const int* __restrict__ dstp) {
    int e = blockIdx.x * blockDim.x + threadIdx.x;
    if (e < N_EDGES) {
        int d = dstp[e];
        int pos = atomicAdd(&g_cursor[d], 1);
        g_srcsorted[pos] = srcp[e];
    }
}

// ---------------- bf16 helpers ---------------------------------------------
__device__ __forceinline__ unsigned pack_bf16(float a, float b) {
    __nv_bfloat162 t = __floats2bfloat162_rn(a, b);
    return *(unsigned*)&t;
}

__device__ __forceinline__ float2 unpack_bf16(unsigned v) {
    __nv_bfloat162 t = *(__nv_bfloat162*)&v;
    return __bfloat1622float2(t);
}

__device__ __forceinline__ void ldsm_x4(unsigned& r0, unsigned& r1,
                                        unsigned& r2, unsigned& r3,
                                        unsigned addr) {
    asm volatile("ldmatrix.sync.aligned.m8n8.x4.shared.b16 {%0,%1,%2,%3}, [%4];"
                 : "=r"(r0), "=r"(r1), "=r"(r2), "=r"(r3) : "r"(addr));
}

__device__ __forceinline__ void ldsm_x4_t(unsigned& r0, unsigned& r1,
                                          unsigned& r2, unsigned& r3,
                                          unsigned addr) {
    asm volatile("ldmatrix.sync.aligned.m8n8.x4.trans.shared.b16 {%0,%1,%2,%3}, [%4];"
                 : "=r"(r0), "=r"(r1), "=r"(r2), "=r"(r3) : "r"(addr));
}

__device__ __forceinline__ void mma_bf16(float* c, const unsigned* a,
                                         unsigned b0, unsigned b1) {
    asm volatile(
        "mma.sync.aligned.m16n8k16.row.col.f32.bf16.bf16.f32 "
        "{%0,%1,%2,%3}, {%4,%5,%6,%7}, {%8,%9}, {%0,%1,%2,%3};\n"
        : "+f"(c[0]), "+f"(c[1]), "+f"(c[2]), "+f"(c[3])
        : "r"(a[0]), "r"(a[1]), "r"(a[2]), "r"(a[3]), "r"(b0), "r"(b1));
}

// ---------------- GEMM (bf16 tensor cores): g16 = bf16(dinv ⊙ (A @ W)) ----
// M=50000, N=K=256. Block 128x128xBK(=16). 8 warps 2(M)x4(N), warp 64x32.
#define BM 128
#define BN 128
#define BK 16
#define APITCH 24   // ushorts: 48B rows -> conflict-free LDSM
#define BPITCH 136  // ushorts: 272B rows -> conflict-free LDSM

// A-tile staging: LAYER 1 loads fp32 x and converts; LAYER 2 loads bf16 h.
template <int LAYER>
__device__ __forceinline__ uint4 stage_a(const float* __restrict__ A,
                                         int gr, bool aOk, int kcol) {
    if (LAYER == 1) {
        float4 a0 = make_float4(0.f, 0.f, 0.f, 0.f), a1 = a0;
        if (aOk) {
            a0 = *(const float4*)&A[(size_t)gr * F + kcol];
            a1 = *(const float4*)&A[(size_t)gr * F + kcol + 4];
        }
        uint4 av;
        av.x = pack_bf16(a0.x, a0.y); av.y = pack_bf16(a0.z, a0.w);
        av.z = pack_bf16(a1.x, a1.y); av.w = pack_bf16(a1.z, a1.w);
        return av;
    } else {
        if (aOk) return *(const uint4*)&h_buf16[(size_t)gr * F2 + (kcol >> 1)];
        return make_uint4(0u, 0u, 0u, 0u);
    }
}

template <int LAYER>
__global__ __launch_bounds__(256) void gemm_bf16_kernel(
        const float* __restrict__ Ain, const float* __restrict__ W) {
    __shared__ __align__(16) unsigned short As[2][BM * APITCH];
    __shared__ __align__(16) unsigned short Bs[2][BK * BPITCH];

    const float* __restrict__ A = Ain;   // only used for LAYER 1
    unsigned* __restrict__ C = g_buf16;

    const int tid   = threadIdx.x;
    const int lane  = tid & 31;
    const int warp  = tid >> 5;
    const int warpM = warp & 1;    // 64-row slab
    const int warpN = warp >> 1;   // 32-col slab
    const int rowBase = blockIdx.x * BM;
    const int colBase = blockIdx.y * BN;

    const int aRow = tid >> 1;        // 0..127
    const int aK   = (tid & 1) * 8;   // bf16 col 0 or 8
    const int gr   = rowBase + aRow;
    const bool aOk = (gr < N_NODES);
    const int bK = tid >> 4;          // 0..15
    const int bN = (tid & 15) * 8;    // 0..120

    float acc[4][4][4];
    #pragma unroll
    for (int mi = 0; mi < 4; mi++)
        #pragma unroll
        for (int ni = 0; ni < 4; ni++)
            #pragma unroll
            for (int q = 0; q < 4; q++) acc[mi][ni][q] = 0.f;

    // ---- prologue: stage tile 0 ----
    {
        uint4 av = stage_a<LAYER>(A, gr, aOk, aK);
        *(uint4*)&As[0][aRow * APITCH + aK] = av;

        float4 b0 = *(const float4*)&W[(size_t)bK * F + colBase + bN];
        float4 b1 = *(const float4*)&W[(size_t)bK * F + colBase + bN + 4];
        uint4 bv;
        bv.x = pack_bf16(b0.x, b0.y); bv.y = pack_bf16(b0.z, b0.w);
        bv.z = pack_bf16(b1.x, b1.y); bv.w = pack_bf16(b1.z, b1.w);
        *(uint4*)&Bs[0][bK * BPITCH + bN] = bv;
    }
    __syncthreads();

    const unsigned asBase = (unsigned)__cvta_generic_to_shared(&As[0][0]);
    const unsigned bsBase = (unsigned)__cvta_generic_to_shared(&Bs[0][0]);
    const unsigned asBuf  = BM * APITCH * 2;
    const unsigned bsBuf  = BK * BPITCH * 2;
    const unsigned aFragOff =
        (unsigned)((warpM * 64 + (lane & 15)) * APITCH + (lane >> 4) * 8) * 2;
    const unsigned bFragOff =
        (unsigned)((lane & 15) * BPITCH + warpN * 32 + (lane >> 4) * 8) * 2;

    int buf = 0;
    #pragma unroll 2
    for (int kt = 0; kt < F / BK; ++kt) {
        const int knext = (kt + 1) * BK;
        uint4 av;
        float4 b0, b1;
        if (knext < F) {
            av = stage_a<LAYER>(A, gr, aOk, knext + aK);
            b0 = *(const float4*)&W[(size_t)(knext + bK) * F + colBase + bN];
            b1 = *(const float4*)&W[(size_t)(knext + bK) * F + colBase + bN + 4];
        }

        unsigned afr[4][4], bfr[2][4];
        #pragma unroll
        for (int mi = 0; mi < 4; mi++)
            ldsm_x4(afr[mi][0], afr[mi][1], afr[mi][2], afr[mi][3],
                    asBase + buf * asBuf + aFragOff + (unsigned)(mi * 16 * APITCH * 2));
        #pragma unroll
        for (int nb = 0; nb < 2; nb++)
            ldsm_x4_t(bfr[nb][0], bfr[nb][1], bfr[nb][2], bfr[nb][3],
                      bsBase + buf * bsBuf + bFragOff + (unsigned)(nb * 16 * 2));

        #pragma unroll
        for (int mi = 0; mi < 4; mi++)
            #pragma unroll
            for (int ni = 0; ni < 4; ni++)
                mma_bf16(acc[mi][ni], afr[mi],
                         bfr[ni >> 1][(ni & 1) * 2], bfr[ni >> 1][(ni & 1) * 2 + 1]);

        if (knext < F) {
            *(uint4*)&As[buf ^ 1][aRow * APITCH + aK] = av;
            uint4 bv;
            bv.x = pack_bf16(b0.x, b0.y); bv.y = pack_bf16(b0.z, b0.w);
            bv.z = pack_bf16(b1.x, b1.y); bv.w = pack_bf16(b1.z, b1.w);
            *(uint4*)&Bs[buf ^ 1][bK * BPITCH + bN] = bv;
        }
        __syncthreads();
        buf ^= 1;
    }

    // ---- epilogue: scale by dinv, store bf16x2 (one u32 per frag pair) ----
    const int g  = lane >> 2;
    const int tg = lane & 3;
    #pragma unroll
    for (int mi = 0; mi < 4; mi++) {
        int r0 = rowBase + warpM * 64 + mi * 16 + g;
        int r1 = r0 + 8;
        float s0 = (r0 < N_NODES) ? g_dinv[r0] : 0.f;
        float s1 = (r1 < N_NODES) ? g_dinv[r1] : 0.f;
        #pragma unroll
        for (int ni = 0; ni < 4; ni++) {
            int c = colBase + warpN * 32 + ni * 8 + 2 * tg;   // even bf16 col
            if (r0 < N_NODES)
                C[(size_t)r0 * F2 + (c >> 1)] =
                    pack_bf16(s0 * acc[mi][ni][0], s0 * acc[mi][ni][1]);
            if (r1 < N_NODES)
                C[(size_t)r1 * F2 + (c >> 1)] =
                    pack_bf16(s1 * acc[mi][ni][2], s1 * acc[mi][ni][3]);
        }
    }
}

// ---------------- SpMM (CSR row-sum) on bf16x2 + bias + ReLU (+residual) --
// 128 threads per node; thread owns 2 feature cols via one u32 load.
template <bool FINAL>
__global__ __launch_bounds__(128) void spmm_kernel(
        const float* __restrict__ bias,
        const float* __restrict__ xres,
        float* __restrict__ outp) {
    const int d = blockIdx.x;
    const int c = threadIdx.x;                 // u32 column 0..127
    const unsigned* __restrict__ g = g_buf16;

    const int s = g_rowstart[d];
    const int e = g_rowstart[d + 1];

    float2 acc = unpack_bf16(g[(size_t)d * F2 + c]);   // self-loop term
    int j = s;
    for (; j + 4 <= e; j += 4) {
        int i0 = g_srcsorted[j + 0];
        int i1 = g_srcsorted[j + 1];
        int i2 = g_srcsorted[j + 2];
        int i3 = g_srcsorted[j + 3];
        unsigned v0 = g[(size_t)i0 * F2 + c];
        unsigned v1 = g[(size_t)i1 * F2 + c];
        unsigned v2 = g[(size_t)i2 * F2 + c];
        unsigned v3 = g[(size_t)i3 * F2 + c];
        float2 f0 = unpack_bf16(v0), f1 = unpack_bf16(v1);
        float2 f2 = unpack_bf16(v2), f3 = unpack_bf16(v3);
        acc.x += (f0.x + f1.x) + (f2.x + f3.x);
        acc.y += (f0.y + f1.y) + (f2.y + f3.y);
    }
    for (; j < e; ++j) {
        float2 f = unpack_bf16(g[(size_t)g_srcsorted[j] * F2 + c]);
        acc.x += f.x; acc.y += f.y;
    }

    const float dv = g_dinv[d];
    const float2 b = *(const float2*)&bias[2 * c];
    float r0 = fmaxf(dv * acc.x + b.x, 0.f);
    float r1 = fmaxf(dv * acc.y + b.y, 0.f);
    if (FINAL) {
        float2 xr = *(const float2*)&xres[(size_t)d * F + 2 * c];
        *(float2*)&outp[(size_t)d * F + 2 * c] =
            make_float2(0.5f * (xr.x + r0), 0.5f * (xr.y + r1));
    } else {
        h_buf16[(size_t)d * F2 + c] = pack_bf16(r0, r1);
    }
}

// ---------------- launch ---------------------------------------------------
extern "C" void kernel_launch(void* const* d_in, const int* in_sizes, int n_in,
                              void* d_out, int out_size) {
    const float* x  = (const float*)d_in[0];
    const int*   ei = (const int*)d_in[1];
    const float* W1 = (const float*)d_in[2];
    const float* b1 = (const float*)d_in[3];
    const float* W2 = (const float*)d_in[4];
    const float* b2 = (const float*)d_in[5];
    float* out = (float*)d_out;

    const int* srcp = ei;             // edge_index[0]
    const int* dstp = ei + N_EDGES;   // edge_index[1]

    const int TB = 256;
    init_counts_kernel<<<(N_NODES + TB - 1) / TB, TB>>>();
    hist_kernel<<<(N_EDGES + TB - 1) / TB, TB>>>(dstp);
    scan_kernel<<<1, 1024>>>();
    setup_kernel<<<(N_NODES + TB - 1) / TB, TB>>>();
    scatter_kernel<<<(N_EDGES + TB - 1) / TB, TB>>>(srcp, dstp);

    dim3 gemm_grid((N_NODES + BM - 1) / BM, F / BN);
    gemm_bf16_kernel<1><<<gemm_grid, 256>>>(x, W1);
    spmm_kernel<false><<<N_NODES, 128>>>(b1, nullptr, nullptr);
    gemm_bf16_kernel<2><<<gemm_grid, 256>>>(nullptr, W2);
    spmm_kernel<true><<<N_NODES, 128>>>(b2, x, out);
}

// round 9
// speedup vs baseline: 2.1763x; 1.0025x over previous
#include <cuda_runtime.h>
#include <cuda_bf16.h>
#include <cstdint>

#define N_NODES 50000
#define N_EDGES 800000
#define F 256
#define F2 (F / 2)

// ---------------- scratch (static device globals; no runtime alloc) -------
__device__ __align__(16) unsigned g_buf16[(size_t)N_NODES * F2];  // bf16x2 msgs
__device__ __align__(16) unsigned h_buf16[(size_t)N_NODES * F2];  // bf16x2 acts
__device__ __align__(16) unsigned Wb16[F * F2];                   // bf16x2 weights
__device__ int   g_counts[N_NODES];
__device__ int   g_rowstart[N_NODES + 1];
__device__ int   g_cursor[N_NODES];
__device__ float g_dinv[N_NODES];
__device__ int   g_srcsorted[N_EDGES];

// ---------------- graph preprocessing -------------------------------------
__global__ void init_counts_kernel() {
    int i = blockIdx.x * blockDim.x + threadIdx.x;
    if (i < N_NODES) g_counts[i] = 0;
}

__global__ void hist_kernel(const int* __restrict__ dstp) {
    int e = blockIdx.x * blockDim.x + threadIdx.x;
    if (e < N_EDGES) atomicAdd(&g_counts[dstp[e]], 1);
}

// single-block exclusive scan of g_counts -> g_rowstart; also dinv + cursor
__global__ void scan_kernel() {
    __shared__ int warpsum[32];
    const int lane = threadIdx.x & 31;
    const int w    = threadIdx.x >> 5;
    int carry = 0;
    for (int base = 0; base < N_NODES; base += 1024) {
        int i = base + threadIdx.x;
        int v = (i < N_NODES) ? g_counts[i] : 0;
        int incl = v;
        #pragma unroll
        for (int o = 1; o < 32; o <<= 1) {
            int t = __shfl_up_sync(0xffffffffu, incl, o);
            if (lane >= o) incl += t;
        }
        if (lane == 31) warpsum[w] = incl;
        __syncthreads();
        if (w == 0) {
            int s = warpsum[lane];
            #pragma unroll
            for (int o = 1; o < 32; o <<= 1) {
                int t = __shfl_up_sync(0xffffffffu, s, o);
                if (lane >= o) s += t;
            }
            warpsum[lane] = s;
        }
        __syncthreads();
        int woff = (w > 0) ? warpsum[w - 1] : 0;
        if (i < N_NODES) {
            int rs = carry + woff + incl - v;
            g_rowstart[i] = rs;
            g_cursor[i]   = rs;                        // fused setup
            g_dinv[i]     = rsqrtf((float)(v + 1));    // fused setup (+self-loop)
        }
        int total = warpsum[31];
        __syncthreads();
        carry += total;
    }
    if (threadIdx.x == 0) g_rowstart[N_NODES] = carry;
}

__global__ void scatter_kernel(const int* __restrict__ srcp,
                               const int* __restrict__ dstp) {
    int e = blockIdx.x * blockDim.x + threadIdx.x;
    if (e < N_EDGES) {
        int d = dstp[e];
        int pos = atomicAdd(&g_cursor[d], 1);
        g_srcsorted[pos] = srcp[e];
    }
}

// ---------------- bf16 helpers ---------------------------------------------
__device__ __forceinline__ unsigned pack_bf16(float a, float b) {
    __nv_bfloat162 t = __floats2bfloat162_rn(a, b);
    return *(unsigned*)&t;
}

__device__ __forceinline__ float2 unpack_bf16(unsigned v) {
    __nv_bfloat162 t = *(__nv_bfloat162*)&v;
    return __bfloat1622float2(t);
}

// W (fp32 [256,256]) -> Wb16 (bf16x2 u32 [256,128])
__global__ void w16_kernel(const float* __restrict__ W) {
    int i = blockIdx.x * blockDim.x + threadIdx.x;   // 0..32767
    if (i < F * F2) {
        float2 v = *(const float2*)&W[2 * i];
        Wb16[i] = pack_bf16(v.x, v.y);
    }
}

__device__ __forceinline__ void ldsm_x4(unsigned& r0, unsigned& r1,
                                        unsigned& r2, unsigned& r3,
                                        unsigned addr) {
    asm volatile("ldmatrix.sync.aligned.m8n8.x4.shared.b16 {%0,%1,%2,%3}, [%4];"
                 : "=r"(r0), "=r"(r1), "=r"(r2), "=r"(r3) : "r"(addr));
}

__device__ __forceinline__ void ldsm_x4_t(unsigned& r0, unsigned& r1,
                                          unsigned& r2, unsigned& r3,
                                          unsigned addr) {
    asm volatile("ldmatrix.sync.aligned.m8n8.x4.trans.shared.b16 {%0,%1,%2,%3}, [%4];"
                 : "=r"(r0), "=r"(r1), "=r"(r2), "=r"(r3) : "r"(addr));
}

__device__ __forceinline__ void mma_bf16(float* c, const unsigned* a,
                                         unsigned b0, unsigned b1) {
    asm volatile(
        "mma.sync.aligned.m16n8k16.row.col.f32.bf16.bf16.f32 "
        "{%0,%1,%2,%3}, {%4,%5,%6,%7}, {%8,%9}, {%0,%1,%2,%3};\n"
        : "+f"(c[0]), "+f"(c[1]), "+f"(c[2]), "+f"(c[3])
        : "r"(a[0]), "r"(a[1]), "r"(a[2]), "r"(a[3]), "r"(b0), "r"(b1));
}

// ---------------- GEMM (bf16 mma.sync): g16 = bf16(dinv ⊙ (A @ W)) --------
// M=50000, N=K=256. Block 128x256xBK(=16). 512 threads, 16 warps 2(M)x8(N),
// warp tile 64x32. Per k-tile per warp: 4 ldsm.x4 (A) + 2 ldsm.x4.t (B),
// 16 MMAs. B staged from pre-converted bf16 Wb16 (1 uint4/thread/k-tile).
#define BM 128
#define BN 256
#define BK 16
#define APITCH 24   // ushorts: 48B rows -> conflict-free LDSM
#define BPITCH 264  // ushorts: 528B rows -> 33r mod 8 = r (conflict-free)

// A-tile staging value: LAYER 1 converts fp32 x; LAYER 2 loads bf16 h.
template <int LAYER>
__device__ __forceinline__ uint4 stage_a(const float* __restrict__ A,
                                         int gr, bool aOk, int kcol) {
    if (LAYER == 1) {
        float4 a0 = make_float4(0.f, 0.f, 0.f, 0.f), a1 = a0;
        if (aOk) {
            a0 = *(const float4*)&A[(size_t)gr * F + kcol];
            a1 = *(const float4*)&A[(size_t)gr * F + kcol + 4];
        }
        uint4 av;
        av.x = pack_bf16(a0.x, a0.y); av.y = pack_bf16(a0.z, a0.w);
        av.z = pack_bf16(a1.x, a1.y); av.w = pack_bf16(a1.z, a1.w);
        return av;
    } else {
        if (aOk) return *(const uint4*)&h_buf16[(size_t)gr * F2 + (kcol >> 1)];
        return make_uint4(0u, 0u, 0u, 0u);
    }
}

template <int LAYER>
__global__ __launch_bounds__(512) void gemm_bf16_kernel(
        const float* __restrict__ Ain) {
    __shared__ __align__(16) unsigned short As[2][BM * APITCH];
    __shared__ __align__(16) unsigned short Bs[2][BK * BPITCH];

    unsigned* __restrict__ C = g_buf16;

    const int tid   = threadIdx.x;
    const int lane  = tid & 31;
    const int warp  = tid >> 5;
    const int warpM = warp & 1;    // 64-row slab
    const int warpN = warp >> 1;   // 0..7 -> 32-col slab
    const int rowBase = blockIdx.x * BM;

    // A staging (threads 0..255): row tid>>1, k-half (tid&1)*8
    const bool aStage = (tid < 256);
    const int aRow = tid >> 1;
    const int aK   = (tid & 1) * 8;
    const int gr   = rowBase + aRow;
    const bool aOk = aStage && (gr < N_NODES);
    // B staging (all 512): k-row tid>>5, 8 bf16 cols at (tid&31)*8
    const int bK  = tid >> 5;          // 0..15
    const int bN  = (tid & 31) * 8;    // 0..248

    float acc[4][4][4];
    #pragma unroll
    for (int mi = 0; mi < 4; mi++)
        #pragma unroll
        for (int ni = 0; ni < 4; ni++)
            #pragma unroll
            for (int q = 0; q < 4; q++) acc[mi][ni][q] = 0.f;

    // ---- prologue: stage tile 0 ----
    {
        if (aStage) {
            uint4 av = stage_a<LAYER>(Ain, gr, aOk, aK);
            *(uint4*)&As[0][aRow * APITCH + aK] = av;
        }
        uint4 bv = *(const uint4*)&Wb16[(size_t)bK * F2 + (bN >> 1)];
        *(uint4*)&Bs[0][bK * BPITCH + bN] = bv;
    }
    __syncthreads();

    const unsigned asBase = (unsigned)__cvta_generic_to_shared(&As[0][0]);
    const unsigned bsBase = (unsigned)__cvta_generic_to_shared(&Bs[0][0]);
    const unsigned asBuf  = BM * APITCH * 2;
    const unsigned bsBuf  = BK * BPITCH * 2;
    const unsigned aFragOff =
        (unsigned)((warpM * 64 + (lane & 15)) * APITCH + (lane >> 4) * 8) * 2;
    const unsigned bFragOff =
        (unsigned)((lane & 15) * BPITCH + warpN * 32 + (lane >> 4) * 8) * 2;

    int buf = 0;
    #pragma unroll 2
    for (int kt = 0; kt < F / BK; ++kt) {
        const int knext = (kt + 1) * BK;
        uint4 av, bv;
        if (knext < F) {
            if (aStage) av = stage_a<LAYER>(Ain, gr, aOk, knext + aK);
            bv = *(const uint4*)&Wb16[(size_t)(knext + bK) * F2 + (bN >> 1)];
        }

        unsigned afr[4][4], bfr[2][4];
        #pragma unroll
        for (int mi = 0; mi < 4; mi++)
            ldsm_x4(afr[mi][0], afr[mi][1], afr[mi][2], afr[mi][3],
                    asBase + buf * asBuf + aFragOff + (unsigned)(mi * 16 * APITCH * 2));
        #pragma unroll
        for (int nb = 0; nb < 2; nb++)
            ldsm_x4_t(bfr[nb][0], bfr[nb][1], bfr[nb][2], bfr[nb][3],
                      bsBase + buf * bsBuf + bFragOff + (unsigned)(nb * 16 * 2));

        #pragma unroll
        for (int mi = 0; mi < 4; mi++)
            #pragma unroll
            for (int ni = 0; ni < 4; ni++)
                mma_bf16(acc[mi][ni], afr[mi],
                         bfr[ni >> 1][(ni & 1) * 2], bfr[ni >> 1][(ni & 1) * 2 + 1]);

        if (knext < F) {
            if (aStage) *(uint4*)&As[buf ^ 1][aRow * APITCH + aK] = av;
            *(uint4*)&Bs[buf ^ 1][bK * BPITCH + bN] = bv;
        }
        __syncthreads();
        buf ^= 1;
    }

    // ---- epilogue: scale by dinv, store bf16x2 (one u32 per frag pair) ----
    const int g  = lane >> 2;
    const int tg = lane & 3;
    #pragma unroll
    for (int mi = 0; mi < 4; mi++) {
        int r0 = rowBase + warpM * 64 + mi * 16 + g;
        int r1 = r0 + 8;
        float s0 = (r0 < N_NODES) ? g_dinv[r0] : 0.f;
        float s1 = (r1 < N_NODES) ? g_dinv[r1] : 0.f;
        #pragma unroll
        for (int ni = 0; ni < 4; ni++) {
            int c = warpN * 32 + ni * 8 + 2 * tg;   // even bf16 col
            if (r0 < N_NODES)
                C[(size_t)r0 * F2 + (c >> 1)] =
                    pack_bf16(s0 * acc[mi][ni][0], s0 * acc[mi][ni][1]);
            if (r1 < N_NODES)
                C[(size_t)r1 * F2 + (c >> 1)] =
                    pack_bf16(s1 * acc[mi][ni][2], s1 * acc[mi][ni][3]);
        }
    }
}

// ---------------- SpMM (CSR row-sum) on bf16x2 + bias + ReLU (+residual) --
template <bool FINAL>
__global__ __launch_bounds__(128) void spmm_kernel(
        const float* __restrict__ bias,
        const float* __restrict__ xres,
        float* __restrict__ outp) {
    const int d = blockIdx.x;
    const int c = threadIdx.x;
    const unsigned* __restrict__ g = g_buf16;

    const int s = g_rowstart[d];
    const int e = g_rowstart[d + 1];

    float2 acc = unpack_bf16(g[(size_t)d * F2 + c]);   // self-loop term
    int j = s;
    for (; j + 4 <= e; j += 4) {
        int i0 = g_srcsorted[j + 0];
        int i1 = g_srcsorted[j + 1];
        int i2 = g_srcsorted[j + 2];
        int i3 = g_srcsorted[j + 3];
        unsigned v0 = g[(size_t)i0 * F2 + c];
        unsigned v1 = g[(size_t)i1 * F2 + c];
        unsigned v2 = g[(size_t)i2 * F2 + c];
        unsigned v3 = g[(size_t)i3 * F2 + c];
        float2 f0 = unpack_bf16(v0), f1 = unpack_bf16(v1);
        float2 f2 = unpack_bf16(v2), f3 = unpack_bf16(v3);
        acc.x += (f0.x + f1.x) + (f2.x + f3.x);
        acc.y += (f0.y + f1.y) + (f2.y + f3.y);
    }
    for (; j < e; ++j) {
        float2 f = unpack_bf16(g[(size_t)g_srcsorted[j] * F2 + c]);
        acc.x += f.x; acc.y += f.y;
    }

    const float dv = g_dinv[d];
    const float2 b = *(const float2*)&bias[2 * c];
    float r0 = fmaxf(dv * acc.x + b.x, 0.f);
    float r1 = fmaxf(dv * acc.y + b.y, 0.f);
    if (FINAL) {
        float2 xr = *(const float2*)&xres[(size_t)d * F + 2 * c];
        *(float2*)&outp[(size_t)d * F + 2 * c] =
            make_float2(0.5f * (xr.x + r0), 0.5f * (xr.y + r1));
    } else {
        h_buf16[(size_t)d * F2 + c] = pack_bf16(r0, r1);
    }
}

// ---------------- launch ---------------------------------------------------
extern "C" void kernel_launch(void* const* d_in, const int* in_sizes, int n_in,
                              void* d_out, int out_size) {
    const float* x  = (const float*)d_in[0];
    const int*   ei = (const int*)d_in[1];
    const float* W1 = (const float*)d_in[2];
    const float* b1 = (const float*)d_in[3];
    const float* W2 = (const float*)d_in[4];
    const float* b2 = (const float*)d_in[5];
    float* out = (float*)d_out;

    const int* srcp = ei;             // edge_index[0]
    const int* dstp = ei + N_EDGES;   // edge_index[1]

    const int TB = 256;
    init_counts_kernel<<<(N_NODES + TB - 1) / TB, TB>>>();
    hist_kernel<<<(N_EDGES + TB - 1) / TB, TB>>>(dstp);
    scan_kernel<<<1, 1024>>>();
    scatter_kernel<<<(N_EDGES + TB - 1) / TB, TB>>>(srcp, dstp);

    const int nblk = (N_NODES + BM - 1) / BM;   // 391
    w16_kernel<<<(F * F2 + 1023) / 1024, 1024>>>(W1);
    gemm_bf16_kernel<1><<<nblk, 512>>>(x);
    spmm_kernel<false><<<N_NODES, 128>>>(b1, nullptr, nullptr);
    w16_kernel<<<(F * F2 + 1023) / 1024, 1024>>>(W2);
    gemm_bf16_kernel<2><<<nblk, 512>>>(nullptr);
    spmm_kernel<true><<<N_NODES, 128>>>(b2, x, out);
}

// round 10
// speedup vs baseline: 2.2474x; 1.0327x over previous
#include <cuda_runtime.h>
#include <cuda_bf16.h>
#include <cstdint>

#define N_NODES 50000
#define N_EDGES 800000
#define F 256
#define F2 (F / 2)

// ---------------- scratch (static device globals; no runtime alloc) -------
__device__ __align__(16) unsigned g_buf16[(size_t)N_NODES * F2];  // bf16x2 msgs (RAW, unscaled)
__device__ __align__(16) unsigned h_buf16[(size_t)N_NODES * F2];  // bf16x2 acts
__device__ __align__(16) unsigned Wb16a[F * F2];                  // bf16x2 W1
__device__ __align__(16) unsigned Wb16b[F * F2];                  // bf16x2 W2
__device__ int   g_counts[N_NODES];
__device__ int   g_rowstart[N_NODES + 1];
__device__ int   g_cursor[N_NODES];
__device__ float g_dinv[N_NODES];
__device__ __align__(16) int2 g_srcw[N_EDGES];    // (src, dinv[src] bits)

// ---------------- graph preprocessing -------------------------------------
__global__ void init_counts_kernel() {
    int i = blockIdx.x * blockDim.x + threadIdx.x;
    if (i < N_NODES) g_counts[i] = 0;
}

__global__ void hist_kernel(const int* __restrict__ dstp) {
    int e = blockIdx.x * blockDim.x + threadIdx.x;
    if (e < N_EDGES) atomicAdd(&g_counts[dstp[e]], 1);
}

// single-block exclusive scan of g_counts -> g_rowstart; also dinv + cursor
__global__ void scan_kernel() {
    __shared__ int warpsum[32];
    const int lane = threadIdx.x & 31;
    const int w    = threadIdx.x >> 5;
    int carry = 0;
    for (int base = 0; base < N_NODES; base += 1024) {
        int i = base + threadIdx.x;
        int v = (i < N_NODES) ? g_counts[i] : 0;
        int incl = v;
        #pragma unroll
        for (int o = 1; o < 32; o <<= 1) {
            int t = __shfl_up_sync(0xffffffffu, incl, o);
            if (lane >= o) incl += t;
        }
        if (lane == 31) warpsum[w] = incl;
        __syncthreads();
        if (w == 0) {
            int s = warpsum[lane];
            #pragma unroll
            for (int o = 1; o < 32; o <<= 1) {
                int t = __shfl_up_sync(0xffffffffu, s, o);
                if (lane >= o) s += t;
            }
            warpsum[lane] = s;
        }
        __syncthreads();
        int woff = (w > 0) ? warpsum[w - 1] : 0;
        if (i < N_NODES) {
            int rs = carry + woff + incl - v;
            g_rowstart[i] = rs;
            g_cursor[i]   = rs;
            g_dinv[i]     = rsqrtf((float)(v + 1));    // +1 self-loop
        }
        int total = warpsum[31];
        __syncthreads();
        carry += total;
    }
    if (threadIdx.x == 0) g_rowstart[N_NODES] = carry;
}

__global__ void scatter_kernel(const int* __restrict__ srcp,
                               const int* __restrict__ dstp) {
    int e = blockIdx.x * blockDim.x + threadIdx.x;
    if (e < N_EDGES) {
        int s = srcp[e];
        int d = dstp[e];
        int pos = atomicAdd(&g_cursor[d], 1);
        g_srcw[pos] = make_int2(s, __float_as_int(g_dinv[s]));
    }
}

// ---------------- bf16 helpers ---------------------------------------------
__device__ __forceinline__ unsigned pack_bf16(float a, float b) {
    __nv_bfloat162 t = __floats2bfloat162_rn(a, b);
    return *(unsigned*)&t;
}

__device__ __forceinline__ float2 unpack_bf16(unsigned v) {
    __nv_bfloat162 t = *(__nv_bfloat162*)&v;
    return __bfloat1622float2(t);
}

// W (fp32 [256,256]) -> bf16x2 u32 [256,128]
__global__ void w16_kernel(const float* __restrict__ W, unsigned* __restrict__ dst) {
    int i = blockIdx.x * blockDim.x + threadIdx.x;
    if (i < F * F2) {
        float2 v = *(const float2*)&W[2 * i];
        dst[i] = pack_bf16(v.x, v.y);
    }
}

__device__ __forceinline__ void ldsm_x4(unsigned& r0, unsigned& r1,
                                        unsigned& r2, unsigned& r3,
                                        unsigned addr) {
    asm volatile("ldmatrix.sync.aligned.m8n8.x4.shared.b16 {%0,%1,%2,%3}, [%4];"
                 : "=r"(r0), "=r"(r1), "=r"(r2), "=r"(r3) : "r"(addr));
}

__device__ __forceinline__ void ldsm_x4_t(unsigned& r0, unsigned& r1,
                                          unsigned& r2, unsigned& r3,
                                          unsigned addr) {
    asm volatile("ldmatrix.sync.aligned.m8n8.x4.trans.shared.b16 {%0,%1,%2,%3}, [%4];"
                 : "=r"(r0), "=r"(r1), "=r"(r2), "=r"(r3) : "r"(addr));
}

__device__ __forceinline__ void mma_bf16(float* c, const unsigned* a,
                                         unsigned b0, unsigned b1) {
    asm volatile(
        "mma.sync.aligned.m16n8k16.row.col.f32.bf16.bf16.f32 "
        "{%0,%1,%2,%3}, {%4,%5,%6,%7}, {%8,%9}, {%0,%1,%2,%3};\n"
        : "+f"(c[0]), "+f"(c[1]), "+f"(c[2]), "+f"(c[3])
        : "r"(a[0]), "r"(a[1]), "r"(a[2]), "r"(a[3]), "r"(b0), "r"(b1));
}

// ---------------- GEMM (bf16 mma.sync): g16_raw = bf16(A @ W) -------------
// No dinv dependency -> runs concurrently with graph preprocessing.
#define BM 128
#define BN 256
#define BK 16
#define APITCH 24   // ushorts: 48B rows -> conflict-free LDSM
#define BPITCH 264  // ushorts: 528B rows -> conflict-free LDSM

template <int LAYER>
__device__ __forceinline__ uint4 stage_a(const float* __restrict__ A,
                                         int gr, bool aOk, int kcol) {
    if (LAYER == 1) {
        float4 a0 = make_float4(0.f, 0.f, 0.f, 0.f), a1 = a0;
        if (aOk) {
            a0 = *(const float4*)&A[(size_t)gr * F + kcol];
            a1 = *(const float4*)&A[(size_t)gr * F + kcol + 4];
        }
        uint4 av;
        av.x = pack_bf16(a0.x, a0.y); av.y = pack_bf16(a0.z, a0.w);
        av.z = pack_bf16(a1.x, a1.y); av.w = pack_bf16(a1.z, a1.w);
        return av;
    } else {
        if (aOk) return *(const uint4*)&h_buf16[(size_t)gr * F2 + (kcol >> 1)];
        return make_uint4(0u, 0u, 0u, 0u);
    }
}

template <int LAYER>
__global__ __launch_bounds__(512) void gemm_bf16_kernel(
        const float* __restrict__ Ain, const unsigned* __restrict__ Wb) {
    __shared__ __align__(16) unsigned short As[2][BM * APITCH];
    __shared__ __align__(16) unsigned short Bs[2][BK * BPITCH];

    unsigned* __restrict__ C = g_buf16;

    const int tid   = threadIdx.x;
    const int lane  = tid & 31;
    const int warp  = tid >> 5;
    const int warpM = warp & 1;
    const int warpN = warp >> 1;
    const int rowBase = blockIdx.x * BM;

    const bool aStage = (tid < 256);
    const int aRow = tid >> 1;
    const int aK   = (tid & 1) * 8;
    const int gr   = rowBase + aRow;
    const bool aOk = aStage && (gr < N_NODES);
    const int bK  = tid >> 5;
    const int bN  = (tid & 31) * 8;

    float acc[4][4][4];
    #pragma unroll
    for (int mi = 0; mi < 4; mi++)
        #pragma unroll
        for (int ni = 0; ni < 4; ni++)
            #pragma unroll
            for (int q = 0; q < 4; q++) acc[mi][ni][q] = 0.f;

    {
        if (aStage) {
            uint4 av = stage_a<LAYER>(Ain, gr, aOk, aK);
            *(uint4*)&As[0][aRow * APITCH + aK] = av;
        }
        uint4 bv = *(const uint4*)&Wb[(size_t)bK * F2 + (bN >> 1)];
        *(uint4*)&Bs[0][bK * BPITCH + bN] = bv;
    }
    __syncthreads();

    const unsigned asBase = (unsigned)__cvta_generic_to_shared(&As[0][0]);
    const unsigned bsBase = (unsigned)__cvta_generic_to_shared(&Bs[0][0]);
    const unsigned asBuf  = BM * APITCH * 2;
    const unsigned bsBuf  = BK * BPITCH * 2;
    const unsigned aFragOff =
        (unsigned)((warpM * 64 + (lane & 15)) * APITCH + (lane >> 4) * 8) * 2;
    const unsigned bFragOff =
        (unsigned)((lane & 15) * BPITCH + warpN * 32 + (lane >> 4) * 8) * 2;

    int buf = 0;
    #pragma unroll 2
    for (int kt = 0; kt < F / BK; ++kt) {
        const int knext = (kt + 1) * BK;
        uint4 av, bv;
        if (knext < F) {
            if (aStage) av = stage_a<LAYER>(Ain, gr, aOk, knext + aK);
            bv = *(const uint4*)&Wb[(size_t)(knext + bK) * F2 + (bN >> 1)];
        }

        unsigned afr[4][4], bfr[2][4];
        #pragma unroll
        for (int mi = 0; mi < 4; mi++)
            ldsm_x4(afr[mi][0], afr[mi][1], afr[mi][2], afr[mi][3],
                    asBase + buf * asBuf + aFragOff + (unsigned)(mi * 16 * APITCH * 2));
        #pragma unroll
        for (int nb = 0; nb < 2; nb++)
            ldsm_x4_t(bfr[nb][0], bfr[nb][1], bfr[nb][2], bfr[nb][3],
                      bsBase + buf * bsBuf + bFragOff + (unsigned)(nb * 16 * 2));

        #pragma unroll
        for (int mi = 0; mi < 4; mi++)
            #pragma unroll
            for (int ni = 0; ni < 4; ni++)
                mma_bf16(acc[mi][ni], afr[mi],
                         bfr[ni >> 1][(ni & 1) * 2], bfr[ni >> 1][(ni & 1) * 2 + 1]);

        if (knext < F) {
            if (aStage) *(uint4*)&As[buf ^ 1][aRow * APITCH + aK] = av;
            *(uint4*)&Bs[buf ^ 1][bK * BPITCH + bN] = bv;
        }
        __syncthreads();
        buf ^= 1;
    }

    // ---- epilogue: store RAW bf16x2 (dinv applied later in SpMM) ----
    const int g  = lane >> 2;
    const int tg = lane & 3;
    #pragma unroll
    for (int mi = 0; mi < 4; mi++) {
        int r0 = rowBase + warpM * 64 + mi * 16 + g;
        int r1 = r0 + 8;
        #pragma unroll
        for (int ni = 0; ni < 4; ni++) {
            int c = warpN * 32 + ni * 8 + 2 * tg;
            if (r0 < N_NODES)
                C[(size_t)r0 * F2 + (c >> 1)] =
                    pack_bf16(acc[mi][ni][0], acc[mi][ni][1]);
            if (r1 < N_NODES)
                C[(size_t)r1 * F2 + (c >> 1)] =
                    pack_bf16(acc[mi][ni][2], acc[mi][ni][3]);
        }
    }
}

// ---------------- SpMM: out[d] = dinv[d]*(Σ dinv[s]·g[s] + dinv[d]·g[d]) --
template <bool FINAL>
__global__ __launch_bounds__(128) void spmm_kernel(
        const float* __restrict__ bias,
        const float* __restrict__ xres,
        float* __restrict__ outp) {
    const int d = blockIdx.x;
    const int c = threadIdx.x;
    const unsigned* __restrict__ g = g_buf16;
    const int2* __restrict__ sw = g_srcw;

    const int s = g_rowstart[d];
    const int e = g_rowstart[d + 1];
    const float dd = g_dinv[d];

    float2 self = unpack_bf16(g[(size_t)d * F2 + c]);
    float2 acc = make_float2(dd * self.x, dd * self.y);   // self-loop term
    int j = s;
    for (; j + 4 <= e; j += 4) {
        int2 p0 = sw[j + 0];
        int2 p1 = sw[j + 1];
        int2 p2 = sw[j + 2];
        int2 p3 = sw[j + 3];
        float2 f0 = unpack_bf16(g[(size_t)p0.x * F2 + c]);
        float2 f1 = unpack_bf16(g[(size_t)p1.x * F2 + c]);
        float2 f2 = unpack_bf16(g[(size_t)p2.x * F2 + c]);
        float2 f3 = unpack_bf16(g[(size_t)p3.x * F2 + c]);
        float w0 = __int_as_float(p0.y), w1 = __int_as_float(p1.y);
        float w2 = __int_as_float(p2.y), w3 = __int_as_float(p3.y);
        acc.x = fmaf(w0, f0.x, acc.x); acc.y = fmaf(w0, f0.y, acc.y);
        acc.x = fmaf(w1, f1.x, acc.x); acc.y = fmaf(w1, f1.y, acc.y);
        acc.x = fmaf(w2, f2.x, acc.x); acc.y = fmaf(w2, f2.y, acc.y);
        acc.x = fmaf(w3, f3.x, acc.x); acc.y = fmaf(w3, f3.y, acc.y);
    }
    for (; j < e; ++j) {
        int2 p = sw[j];
        float2 f = unpack_bf16(g[(size_t)p.x * F2 + c]);
        float w = __int_as_float(p.y);
        acc.x = fmaf(w, f.x, acc.x); acc.y = fmaf(w, f.y, acc.y);
    }

    const float2 b = *(const float2*)&bias[2 * c];
    float r0 = fmaxf(dd * acc.x + b.x, 0.f);
    float r1 = fmaxf(dd * acc.y + b.y, 0.f);
    if (FINAL) {
        float2 xr = *(const float2*)&xres[(size_t)d * F + 2 * c];
        *(float2*)&outp[(size_t)d * F + 2 * c] =
            make_float2(0.5f * (xr.x + r0), 0.5f * (xr.y + r1));
    } else {
        h_buf16[(size_t)d * F2 + c] = pack_bf16(r0, r1);
    }
}

// ---------------- launch ---------------------------------------------------
extern "C" void kernel_launch(void* const* d_in, const int* in_sizes, int n_in,
                              void* d_out, int out_size) {
    const float* x  = (const float*)d_in[0];
    const int*   ei = (const int*)d_in[1];
    const float* W1 = (const float*)d_in[2];
    const float* b1 = (const float*)d_in[3];
    const float* W2 = (const float*)d_in[4];
    const float* b2 = (const float*)d_in[5];
    float* out = (float*)d_out;

    const int* srcp = ei;             // edge_index[0]
    const int* dstp = ei + N_EDGES;   // edge_index[1]

    const int TB = 256;
    const int nblk = (N_NODES + BM - 1) / BM;   // 391

    // device globals referenced from host launches
    unsigned *wa_ptr = nullptr, *wb_ptr = nullptr;
    cudaGetSymbolAddress((void**)&wa_ptr, Wb16a);
    cudaGetSymbolAddress((void**)&wb_ptr, Wb16b);

    // Try forked-stream schedule: prep runs concurrently with gemm1.
    cudaStream_t s2 = 0;
    cudaEvent_t eF = 0, eJ = 0;
    bool forked =
        (cudaStreamCreateWithFlags(&s2, cudaStreamNonBlocking) == cudaSuccess) &&
        (cudaEventCreateWithFlags(&eF, cudaEventDisableTiming) == cudaSuccess) &&
        (cudaEventCreateWithFlags(&eJ, cudaEventDisableTiming) == cudaSuccess);

    if (forked) {
        w16_kernel<<<32, 1024>>>(W1, wa_ptr);                       // idx 0
        w16_kernel<<<32, 1024>>>(W2, wb_ptr);                       // idx 1
        cudaEventRecord(eF, 0);
        cudaStreamWaitEvent(s2, eF, 0);
        init_counts_kernel<<<(N_NODES + TB - 1) / TB, TB, 0, s2>>>();          // idx 2
        gemm_bf16_kernel<1><<<nblk, 512>>>(x, wa_ptr);              // idx 3 (profiled)
        hist_kernel<<<(N_EDGES + TB - 1) / TB, TB, 0, s2>>>(dstp);             // idx 4
        scan_kernel<<<1, 1024, 0, s2>>>();                                     // idx 5
        scatter_kernel<<<(N_EDGES + TB - 1) / TB, TB, 0, s2>>>(srcp, dstp);    // idx 6
        cudaEventRecord(eJ, s2);
        cudaStreamWaitEvent(0, eJ, 0);
        spmm_kernel<false><<<N_NODES, 128>>>(b1, nullptr, nullptr); // idx 7
        gemm_bf16_kernel<2><<<nblk, 512>>>(nullptr, wb_ptr);        // idx 8
        spmm_kernel<true><<<N_NODES, 128>>>(b2, x, out);            // idx 9
    } else {
        // serial fallback
        w16_kernel<<<32, 1024>>>(W1, wa_ptr);
        w16_kernel<<<32, 1024>>>(W2, wb_ptr);
        init_counts_kernel<<<(N_NODES + TB - 1) / TB, TB>>>();
        hist_kernel<<<(N_EDGES + TB - 1) / TB, TB>>>(dstp);
        scan_kernel<<<1, 1024>>>();
        scatter_kernel<<<(N_EDGES + TB - 1) / TB, TB>>>(srcp, dstp);
        gemm_bf16_kernel<1><<<nblk, 512>>>(x, wa_ptr);
        spmm_kernel<false><<<N_NODES, 128>>>(b1, nullptr, nullptr);
        gemm_bf16_kernel<2><<<nblk, 512>>>(nullptr, wb_ptr);
        spmm_kernel<true><<<N_NODES, 128>>>(b2, x, out);
    }
}

// round 11
// speedup vs baseline: 2.3678x; 1.0536x over previous
#include <cuda_runtime.h>
#include <cuda_bf16.h>
#include <cstdint>

#define N_NODES 50000
#define N_EDGES 800000
#define F 256
#define F2 (F / 2)

// ---------------- scratch (static device globals; no runtime alloc) -------
__device__ __align__(16) unsigned g_buf16[(size_t)N_NODES * F2];  // bf16x2 msgs (RAW)
__device__ __align__(16) unsigned h_buf16[(size_t)N_NODES * F2];  // bf16x2 acts
__device__ __align__(16) unsigned Wb16a[F * F2];                  // bf16x2 W1
__device__ __align__(16) unsigned Wb16b[F * F2];                  // bf16x2 W2
__device__ int   g_counts[N_NODES];
__device__ int   g_rowstart[N_NODES + 1];
__device__ int   g_cursor[N_NODES];
__device__ float g_dinv[N_NODES];
__device__ __align__(16) int2 g_srcw[N_EDGES];    // (src, dinv[src] bits)

// ---------------- graph preprocessing -------------------------------------
__global__ void init_counts_kernel() {
    int i = blockIdx.x * blockDim.x + threadIdx.x;
    if (i < N_NODES) g_counts[i] = 0;
}

__global__ void hist_kernel(const int* __restrict__ dstp) {
    int e = blockIdx.x * blockDim.x + threadIdx.x;
    if (e < N_EDGES) atomicAdd(&g_counts[dstp[e]], 1);
}

// single-block exclusive scan of g_counts -> g_rowstart; also dinv + cursor
__global__ void scan_kernel() {
    __shared__ int warpsum[32];
    const int lane = threadIdx.x & 31;
    const int w    = threadIdx.x >> 5;
    int carry = 0;
    for (int base = 0; base < N_NODES; base += 1024) {
        int i = base + threadIdx.x;
        int v = (i < N_NODES) ? g_counts[i] : 0;
        int incl = v;
        #pragma unroll
        for (int o = 1; o < 32; o <<= 1) {
            int t = __shfl_up_sync(0xffffffffu, incl, o);
            if (lane >= o) incl += t;
        }
        if (lane == 31) warpsum[w] = incl;
        __syncthreads();
        if (w == 0) {
            int s = warpsum[lane];
            #pragma unroll
            for (int o = 1; o < 32; o <<= 1) {
                int t = __shfl_up_sync(0xffffffffu, s, o);
                if (lane >= o) s += t;
            }
            warpsum[lane] = s;
        }
        __syncthreads();
        int woff = (w > 0) ? warpsum[w - 1] : 0;
        if (i < N_NODES) {
            int rs = carry + woff + incl - v;
            g_rowstart[i] = rs;
            g_cursor[i]   = rs;
            g_dinv[i]     = rsqrtf((float)(v + 1));    // +1 self-loop
        }
        int total = warpsum[31];
        __syncthreads();
        carry += total;
    }
    if (threadIdx.x == 0) g_rowstart[N_NODES] = carry;
}

__global__ void scatter_kernel(const int* __restrict__ srcp,
                               const int* __restrict__ dstp) {
    int e = blockIdx.x * blockDim.x + threadIdx.x;
    if (e < N_EDGES) {
        int s = srcp[e];
        int d = dstp[e];
        int pos = atomicAdd(&g_cursor[d], 1);
        g_srcw[pos] = make_int2(s, __float_as_int(g_dinv[s]));
    }
}

// ---------------- bf16 helpers ---------------------------------------------
__device__ __forceinline__ unsigned pack_bf16(float a, float b) {
    __nv_bfloat162 t = __floats2bfloat162_rn(a, b);
    return *(unsigned*)&t;
}

__device__ __forceinline__ float2 unpack_bf16(unsigned v) {
    __nv_bfloat162 t = *(__nv_bfloat162*)&v;
    return __bfloat1622float2(t);
}

// W (fp32 [256,256]) -> bf16x2 u32 [256,128]
__global__ void w16_kernel(const float* __restrict__ W, unsigned* __restrict__ dst) {
    int i = blockIdx.x * blockDim.x + threadIdx.x;
    if (i < F * F2) {
        float2 v = *(const float2*)&W[2 * i];
        dst[i] = pack_bf16(v.x, v.y);
    }
}

__device__ __forceinline__ void ldsm_x4(unsigned& r0, unsigned& r1,
                                        unsigned& r2, unsigned& r3,
                                        unsigned addr) {
    asm volatile("ldmatrix.sync.aligned.m8n8.x4.shared.b16 {%0,%1,%2,%3}, [%4];"
                 : "=r"(r0), "=r"(r1), "=r"(r2), "=r"(r3) : "r"(addr));
}

__device__ __forceinline__ void ldsm_x4_t(unsigned& r0, unsigned& r1,
                                          unsigned& r2, unsigned& r3,
                                          unsigned addr) {
    asm volatile("ldmatrix.sync.aligned.m8n8.x4.trans.shared.b16 {%0,%1,%2,%3}, [%4];"
                 : "=r"(r0), "=r"(r1), "=r"(r2), "=r"(r3) : "r"(addr));
}

__device__ __forceinline__ void mma_bf16(float* c, const unsigned* a,
                                         unsigned b0, unsigned b1) {
    asm volatile(
        "mma.sync.aligned.m16n8k16.row.col.f32.bf16.bf16.f32 "
        "{%0,%1,%2,%3}, {%4,%5,%6,%7}, {%8,%9}, {%0,%1,%2,%3};\n"
        : "+f"(c[0]), "+f"(c[1]), "+f"(c[2]), "+f"(c[3])
        : "r"(a[0]), "r"(a[1]), "r"(a[2]), "r"(a[3]), "r"(b0), "r"(b1));
}

// ---------------- GEMM (bf16 mma.sync, fully smem-resident, barrier-free) --
// M=50000, N=K=256. CTA: 128 rows x 256 cols. 512 threads, 16 warps 2(M)x8(N),
// warp tile 64x32. A[128][256] and B[256][256] both fully staged in smem with
// pitch 264 (conflict-free LDSM); ONE __syncthreads, then 16 k-steps of pure
// ldmatrix+mma with no barriers.
#define BM 128
#define BN 256
#define PITCH 264   // ushorts: 528B rows -> 33r mod 8 = r (conflict-free)
#define SMEM_A_WORDS (BM * PITCH)             // 33792 ushorts = 67584 B
#define SMEM_B_WORDS (F * PITCH)              // 67584 ushorts = 135168 B
#define SMEM_BYTES ((SMEM_A_WORDS + SMEM_B_WORDS) * 2)   // 202752 B

template <int LAYER>
__global__ __launch_bounds__(512) void gemm_bf16_kernel(
        const float* __restrict__ Ain, const unsigned* __restrict__ Wb) {
    extern __shared__ __align__(16) unsigned short sm[];
    unsigned short* As = sm;                    // [128][PITCH]
    unsigned short* Bs = sm + SMEM_A_WORDS;     // [256][PITCH] (k-major)

    unsigned* __restrict__ C = g_buf16;

    const int tid   = threadIdx.x;
    const int lane  = tid & 31;
    const int warp  = tid >> 5;
    const int warpM = warp & 1;
    const int warpN = warp >> 1;
    const int rowBase = blockIdx.x * BM;

    // ---- stage A (full 128x256) ----
    if (LAYER == 1) {
        // 8192 float4 total: 16 per thread
        #pragma unroll
        for (int it = 0; it < 16; ++it) {
            int fidx = it * 512 + tid;
            int m  = fidx >> 6;
            int fc = fidx & 63;               // float4 index in row
            int gr = rowBase + m;
            float4 v = make_float4(0.f, 0.f, 0.f, 0.f);
            if (gr < N_NODES) v = *(const float4*)&Ain[(size_t)gr * F + fc * 4];
            uint2 pv;
            pv.x = pack_bf16(v.x, v.y);
            pv.y = pack_bf16(v.z, v.w);
            *(uint2*)&As[m * PITCH + fc * 4] = pv;
        }
    } else {
        // 4096 uint4 total: 8 per thread
        #pragma unroll
        for (int it = 0; it < 8; ++it) {
            int qidx = it * 512 + tid;
            int m  = qidx >> 5;
            int qc = qidx & 31;               // uint4 index in row
            int gr = rowBase + m;
            uint4 v = make_uint4(0u, 0u, 0u, 0u);
            if (gr < N_NODES) v = *(const uint4*)&h_buf16[(size_t)gr * F2 + qc * 4];
            *(uint4*)&As[m * PITCH + qc * 8] = v;
        }
    }

    // ---- stage B (full 256x256, k-major rows) ----
    #pragma unroll
    for (int it = 0; it < 16; ++it) {
        int qidx = it * 512 + tid;
        int k  = qidx >> 5;                   // 0..255
        int qc = qidx & 31;
        uint4 v = *(const uint4*)&Wb[(size_t)k * F2 + qc * 4];
        *(uint4*)&Bs[k * PITCH + qc * 8] = v;
    }
    __syncthreads();   // the ONLY barrier

    // ---- mainloop: 16 k-steps, no barriers ----
    const unsigned asBase = (unsigned)__cvta_generic_to_shared(As);
    const unsigned bsBase = (unsigned)__cvta_generic_to_shared(Bs);
    const unsigned aOff =
        asBase + (unsigned)((warpM * 64 + (lane & 15)) * PITCH + (lane >> 4) * 8) * 2;
    const unsigned bOff =
        bsBase + (unsigned)((lane & 15) * PITCH + warpN * 32 + (lane >> 4) * 8) * 2;

    float acc[4][4][4];
    #pragma unroll
    for (int mi = 0; mi < 4; mi++)
        #pragma unroll
        for (int ni = 0; ni < 4; ni++)
            #pragma unroll
            for (int q = 0; q < 4; q++) acc[mi][ni][q] = 0.f;

    #pragma unroll 2
    for (int kt = 0; kt < F / 16; ++kt) {
        unsigned afr[4][4], bfr[2][4];
        const unsigned ak = aOff + (unsigned)(kt * 16) * 2;           // k cols
        const unsigned bk = bOff + (unsigned)(kt * 16 * PITCH) * 2;   // k rows
        #pragma unroll
        for (int mi = 0; mi < 4; mi++)
            ldsm_x4(afr[mi][0], afr[mi][1], afr[mi][2], afr[mi][3],
                    ak + (unsigned)(mi * 16 * PITCH) * 2);
        #pragma unroll
        for (int nb = 0; nb < 2; nb++)
            ldsm_x4_t(bfr[nb][0], bfr[nb][1], bfr[nb][2], bfr[nb][3],
                      bk + (unsigned)(nb * 16) * 2);
        #pragma unroll
        for (int mi = 0; mi < 4; mi++)
            #pragma unroll
            for (int ni = 0; ni < 4; ni++)
                mma_bf16(acc[mi][ni], afr[mi],
                         bfr[ni >> 1][(ni & 1) * 2], bfr[ni >> 1][(ni & 1) * 2 + 1]);
    }

    // ---- epilogue: store RAW bf16x2 (dinv applied in SpMM) ----
    const int g  = lane >> 2;
    const int tg = lane & 3;
    #pragma unroll
    for (int mi = 0; mi < 4; mi++) {
        int r0 = rowBase + warpM * 64 + mi * 16 + g;
        int r1 = r0 + 8;
        #pragma unroll
        for (int ni = 0; ni < 4; ni++) {
            int c = warpN * 32 + ni * 8 + 2 * tg;
            if (r0 < N_NODES)
                C[(size_t)r0 * F2 + (c >> 1)] =
                    pack_bf16(acc[mi][ni][0], acc[mi][ni][1]);
            if (r1 < N_NODES)
                C[(size_t)r1 * F2 + (c >> 1)] =
                    pack_bf16(acc[mi][ni][2], acc[mi][ni][3]);
        }
    }
}

// ---------------- SpMM: out[d] = dinv[d]*(Σ dinv[s]·g[s] + dinv[d]·g[d]) --
template <bool FINAL>
__global__ __launch_bounds__(128) void spmm_kernel(
        const float* __restrict__ bias,
        const float* __restrict__ xres,
        float* __restrict__ outp) {
    const int d = blockIdx.x;
    const int c = threadIdx.x;
    const unsigned* __restrict__ g = g_buf16;
    const int2* __restrict__ sw = g_srcw;

    const int s = g_rowstart[d];
    const int e = g_rowstart[d + 1];
    const float dd = g_dinv[d];

    float2 self = unpack_bf16(g[(size_t)d * F2 + c]);
    float2 acc = make_float2(dd * self.x, dd * self.y);   // self-loop term
    int j = s;
    for (; j + 4 <= e; j += 4) {
        int2 p0 = sw[j + 0];
        int2 p1 = sw[j + 1];
        int2 p2 = sw[j + 2];
        int2 p3 = sw[j + 3];
        float2 f0 = unpack_bf16(g[(size_t)p0.x * F2 + c]);
        float2 f1 = unpack_bf16(g[(size_t)p1.x * F2 + c]);
        float2 f2 = unpack_bf16(g[(size_t)p2.x * F2 + c]);
        float2 f3 = unpack_bf16(g[(size_t)p3.x * F2 + c]);
        float w0 = __int_as_float(p0.y), w1 = __int_as_float(p1.y);
        float w2 = __int_as_float(p2.y), w3 = __int_as_float(p3.y);
        acc.x = fmaf(w0, f0.x, acc.x); acc.y = fmaf(w0, f0.y, acc.y);
        acc.x = fmaf(w1, f1.x, acc.x); acc.y = fmaf(w1, f1.y, acc.y);
        acc.x = fmaf(w2, f2.x, acc.x); acc.y = fmaf(w2, f2.y, acc.y);
        acc.x = fmaf(w3, f3.x, acc.x); acc.y = fmaf(w3, f3.y, acc.y);
    }
    for (; j < e; ++j) {
        int2 p = sw[j];
        float2 f = unpack_bf16(g[(size_t)p.x * F2 + c]);
        float w = __int_as_float(p.y);
        acc.x = fmaf(w, f.x, acc.x); acc.y = fmaf(w, f.y, acc.y);
    }

    const float2 b = *(const float2*)&bias[2 * c];
    float r0 = fmaxf(dd * acc.x + b.x, 0.f);
    float r1 = fmaxf(dd * acc.y + b.y, 0.f);
    if (FINAL) {
        float2 xr = *(const float2*)&xres[(size_t)d * F + 2 * c];
        *(float2*)&outp[(size_t)d * F + 2 * c] =
            make_float2(0.5f * (xr.x + r0), 0.5f * (xr.y + r1));
    } else {
        h_buf16[(size_t)d * F2 + c] = pack_bf16(r0, r1);
    }
}

// ---------------- launch ---------------------------------------------------
extern "C" void kernel_launch(void* const* d_in, const int* in_sizes, int n_in,
                              void* d_out, int out_size) {
    const float* x  = (const float*)d_in[0];
    const int*   ei = (const int*)d_in[1];
    const float* W1 = (const float*)d_in[2];
    const float* b1 = (const float*)d_in[3];
    const float* W2 = (const float*)d_in[4];
    const float* b2 = (const float*)d_in[5];
    float* out = (float*)d_out;

    const int* srcp = ei;             // edge_index[0]
    const int* dstp = ei + N_EDGES;   // edge_index[1]

    const int TB = 256;
    const int nblk = (N_NODES + BM - 1) / BM;   // 391

    unsigned *wa_ptr = nullptr, *wb_ptr = nullptr;
    cudaGetSymbolAddress((void**)&wa_ptr, Wb16a);
    cudaGetSymbolAddress((void**)&wb_ptr, Wb16b);

    cudaFuncSetAttribute(gemm_bf16_kernel<1>,
                         cudaFuncAttributeMaxDynamicSharedMemorySize, SMEM_BYTES);
    cudaFuncSetAttribute(gemm_bf16_kernel<2>,
                         cudaFuncAttributeMaxDynamicSharedMemorySize, SMEM_BYTES);

    // Forked-stream schedule: prep runs concurrently with gemm1.
    cudaStream_t s2 = 0;
    cudaEvent_t eF = 0, eJ = 0;
    bool forked =
        (cudaStreamCreateWithFlags(&s2, cudaStreamNonBlocking) == cudaSuccess) &&
        (cudaEventCreateWithFlags(&eF, cudaEventDisableTiming) == cudaSuccess) &&
        (cudaEventCreateWithFlags(&eJ, cudaEventDisableTiming) == cudaSuccess);

    if (forked) {
        w16_kernel<<<32, 1024>>>(W1, wa_ptr);                       // idx 0
        w16_kernel<<<32, 1024>>>(W2, wb_ptr);                       // idx 1
        cudaEventRecord(eF, 0);
        cudaStreamWaitEvent(s2, eF, 0);
        init_counts_kernel<<<(N_NODES + TB - 1) / TB, TB, 0, s2>>>();          // idx 2
        gemm_bf16_kernel<1><<<nblk, 512, SMEM_BYTES>>>(x, wa_ptr);  // idx 3 (profiled)
        hist_kernel<<<(N_EDGES + TB - 1) / TB, TB, 0, s2>>>(dstp);             // idx 4
        scan_kernel<<<1, 1024, 0, s2>>>();                                     // idx 5
        scatter_kernel<<<(N_EDGES + TB - 1) / TB, TB, 0, s2>>>(srcp, dstp);    // idx 6
        cudaEventRecord(eJ, s2);
        cudaStreamWaitEvent(0, eJ, 0);
        spmm_kernel<false><<<N_NODES, 128>>>(b1, nullptr, nullptr); // idx 7
        gemm_bf16_kernel<2><<<nblk, 512, SMEM_BYTES>>>(nullptr, wb_ptr);  // idx 8
        spmm_kernel<true><<<N_NODES, 128>>>(b2, x, out);            // idx 9
    } else {
        // serial fallback
        w16_kernel<<<32, 1024>>>(W1, wa_ptr);
        w16_kernel<<<32, 1024>>>(W2, wb_ptr);
        init_counts_kernel<<<(N_NODES + TB - 1) / TB, TB>>>();
        hist_kernel<<<(N_EDGES + TB - 1) / TB, TB>>>(dstp);
        scan_kernel<<<1, 1024>>>();
        scatter_kernel<<<(N_EDGES + TB - 1) / TB, TB>>>(srcp, dstp);
        gemm_bf16_kernel<1><<<nblk, 512, SMEM_BYTES>>>(x, wa_ptr);
        spmm_kernel<false><<<N_NODES, 128>>>(b1, nullptr, nullptr);
        gemm_bf16_kernel<2><<<nblk, 512, SMEM_BYTES>>>(nullptr, wb_ptr);
        spmm_kernel<true><<<N_NODES, 128>>>(b2, x, out);
    }
}

// round 12
// speedup vs baseline: 2.6360x; 1.1133x over previous
#include <cuda_runtime.h>
#include <cuda_bf16.h>
#include <cstdint>

#define N_NODES 50000
#define N_EDGES 800000
#define F 256
#define F2 (F / 2)
#define NCHUNK 196   // ceil(50000/256)

// ---------------- scratch (static device globals; no runtime alloc) -------
__device__ __align__(16) unsigned g_buf16[(size_t)N_NODES * F2];  // bf16x2 msgs (RAW)
__device__ __align__(16) unsigned h_buf16[(size_t)N_NODES * F2];  // bf16x2 acts
__device__ __align__(16) unsigned Wb16a[F * F2];                  // bf16x2 W1
__device__ __align__(16) unsigned Wb16b[F * F2];                  // bf16x2 W2
__device__ int   g_counts[N_NODES];
__device__ int   g_rowstart[N_NODES + 1];
__device__ int   g_cursor[N_NODES];
__device__ float g_dinv[N_NODES];
__device__ int   g_blocksum[NCHUNK];
__device__ int   g_blockoff[NCHUNK];
__device__ __align__(16) int2 g_srcw[N_EDGES];    // (src, dinv[src] bits)

// ---------------- graph preprocessing -------------------------------------
__global__ void init_counts_kernel() {
    int i = blockIdx.x * blockDim.x + threadIdx.x;
    if (i < N_NODES) g_counts[i] = 0;
}

__global__ void hist_kernel(const int* __restrict__ dstp) {
    int e = blockIdx.x * blockDim.x + threadIdx.x;
    if (e < N_EDGES) atomicAdd(&g_counts[dstp[e]], 1);
}

// --- 3-phase multi-block exclusive scan of g_counts -> g_rowstart ---------
__global__ void scanA_kernel() {   // per-chunk sums
    __shared__ int ws[8];
    int b = blockIdx.x;
    int i = b * 256 + threadIdx.x;
    int v = (i < N_NODES) ? g_counts[i] : 0;
    #pragma unroll
    for (int o = 16; o; o >>= 1) v += __shfl_down_sync(0xffffffffu, v, o);
    if ((threadIdx.x & 31) == 0) ws[threadIdx.x >> 5] = v;
    __syncthreads();
    if (threadIdx.x < 8) {
        int s = ws[threadIdx.x];
        #pragma unroll
        for (int o = 4; o; o >>= 1) s += __shfl_down_sync(0xffu, s, o);
        if (threadIdx.x == 0) g_blocksum[b] = s;
    }
}

__global__ void scanB_kernel() {   // scan the 196 chunk sums
    __shared__ int ws[8];
    int t = threadIdx.x;           // 0..255
    int lane = t & 31, w = t >> 5;
    int v = (t < NCHUNK) ? g_blocksum[t] : 0;
    int incl = v;
    #pragma unroll
    for (int o = 1; o < 32; o <<= 1) {
        int x = __shfl_up_sync(0xffffffffu, incl, o);
        if (lane >= o) incl += x;
    }
    if (lane == 31) ws[w] = incl;
    __syncthreads();
    if (w == 0 && lane < 8) {
        int s = ws[lane];
        #pragma unroll
        for (int o = 1; o < 8; o <<= 1) {
            int x = __shfl_up_sync(0xffu, s, o);
            if (lane >= o) s += x;
        }
        ws[lane] = s;
    }
    __syncthreads();
    int off = (w > 0) ? ws[w - 1] : 0;
    if (t < NCHUNK) g_blockoff[t] = off + incl - v;
    if (t == 0) g_rowstart[N_NODES] = N_EDGES;
}

__global__ void scanC_kernel() {   // local scan + rowstart/cursor/dinv
    __shared__ int ws[8];
    int b = blockIdx.x;
    int i = b * 256 + threadIdx.x;
    int v = (i < N_NODES) ? g_counts[i] : 0;
    int lane = threadIdx.x & 31, w = threadIdx.x >> 5;
    int incl = v;
    #pragma unroll
    for (int o = 1; o < 32; o <<= 1) {
        int x = __shfl_up_sync(0xffffffffu, incl, o);
        if (lane >= o) incl += x;
    }
    if (lane == 31) ws[w] = incl;
    __syncthreads();
    if (w == 0 && lane < 8) {
        int s = ws[lane];
        #pragma unroll
        for (int o = 1; o < 8; o <<= 1) {
            int x = __shfl_up_sync(0xffu, s, o);
            if (lane >= o) s += x;
        }
        ws[lane] = s;
    }
    __syncthreads();
    int woff = (w > 0) ? ws[w - 1] : 0;
    if (i < N_NODES) {
        int rs = g_blockoff[b] + woff + incl - v;
        g_rowstart[i] = rs;
        g_cursor[i]   = rs;
        g_dinv[i]     = rsqrtf((float)(v + 1));   // +1 self-loop
    }
}

__global__ void scatter_kernel(const int* __restrict__ srcp,
                               const int* __restrict__ dstp) {
    int e = blockIdx.x * blockDim.x + threadIdx.x;
    if (e < N_EDGES) {
        int s = srcp[e];
        int d = dstp[e];
        int pos = atomicAdd(&g_cursor[d], 1);
        g_srcw[pos] = make_int2(s, __float_as_int(g_dinv[s]));
    }
}

// ---------------- bf16 helpers ---------------------------------------------
__device__ __forceinline__ unsigned pack_bf16(float a, float b) {
    __nv_bfloat162 t = __floats2bfloat162_rn(a, b);
    return *(unsigned*)&t;
}

__device__ __forceinline__ float2 unpack_bf16(unsigned v) {
    __nv_bfloat162 t = *(__nv_bfloat162*)&v;
    return __bfloat1622float2(t);
}

// W (fp32 [256,256]) -> bf16x2 u32 [256,128]
__global__ void w16_kernel(const float* __restrict__ W, unsigned* __restrict__ dst) {
    int i = blockIdx.x * blockDim.x + threadIdx.x;
    if (i < F * F2) {
        float2 v = *(const float2*)&W[2 * i];
        dst[i] = pack_bf16(v.x, v.y);
    }
}

__device__ __forceinline__ void ldsm_x4(unsigned& r0, unsigned& r1,
                                        unsigned& r2, unsigned& r3,
                                        unsigned addr) {
    asm volatile("ldmatrix.sync.aligned.m8n8.x4.shared.b16 {%0,%1,%2,%3}, [%4];"
                 : "=r"(r0), "=r"(r1), "=r"(r2), "=r"(r3) : "r"(addr));
}

__device__ __forceinline__ void ldsm_x4_t(unsigned& r0, unsigned& r1,
                                          unsigned& r2, unsigned& r3,
                                          unsigned addr) {
    asm volatile("ldmatrix.sync.aligned.m8n8.x4.trans.shared.b16 {%0,%1,%2,%3}, [%4];"
                 : "=r"(r0), "=r"(r1), "=r"(r2), "=r"(r3) : "r"(addr));
}

__device__ __forceinline__ void mma_bf16(float* c, const unsigned* a,
                                         unsigned b0, unsigned b1) {
    asm volatile(
        "mma.sync.aligned.m16n8k16.row.col.f32.bf16.bf16.f32 "
        "{%0,%1,%2,%3}, {%4,%5,%6,%7}, {%8,%9}, {%0,%1,%2,%3};\n"
        : "+f"(c[0]), "+f"(c[1]), "+f"(c[2]), "+f"(c[3])
        : "r"(a[0]), "r"(a[1]), "r"(a[2]), "r"(a[3]), "r"(b0), "r"(b1));
}

// ---------------- GEMM (bf16 mma.sync, fully smem-resident, barrier-free) --
#define BM 128
#define BN 256
#define PITCH 264   // ushorts: 528B rows -> 33r mod 8 = r (conflict-free)
#define SMEM_A_WORDS (BM * PITCH)
#define SMEM_B_WORDS (F * PITCH)
#define SMEM_BYTES ((SMEM_A_WORDS + SMEM_B_WORDS) * 2)   // 202752 B

template <int LAYER>
__global__ __launch_bounds__(512) void gemm_bf16_kernel(
        const float* __restrict__ Ain, const unsigned* __restrict__ Wb) {
    extern __shared__ __align__(16) unsigned short sm[];
    unsigned short* As = sm;                    // [128][PITCH]
    unsigned short* Bs = sm + SMEM_A_WORDS;     // [256][PITCH] (k-major)

    unsigned* __restrict__ C = g_buf16;

    const int tid   = threadIdx.x;
    const int lane  = tid & 31;
    const int warp  = tid >> 5;
    const int warpM = warp & 1;
    const int warpN = warp >> 1;
    const int rowBase = blockIdx.x * BM;

    // ---- stage A (full 128x256) ----
    if (LAYER == 1) {
        #pragma unroll
        for (int it = 0; it < 16; ++it) {
            int fidx = it * 512 + tid;
            int m  = fidx >> 6;
            int fc = fidx & 63;
            int gr = rowBase + m;
            float4 v = make_float4(0.f, 0.f, 0.f, 0.f);
            if (gr < N_NODES) v = *(const float4*)&Ain[(size_t)gr * F + fc * 4];
            uint2 pv;
            pv.x = pack_bf16(v.x, v.y);
            pv.y = pack_bf16(v.z, v.w);
            *(uint2*)&As[m * PITCH + fc * 4] = pv;
        }
    } else {
        #pragma unroll
        for (int it = 0; it < 8; ++it) {
            int qidx = it * 512 + tid;
            int m  = qidx >> 5;
            int qc = qidx & 31;
            int gr = rowBase + m;
            uint4 v = make_uint4(0u, 0u, 0u, 0u);
            if (gr < N_NODES) v = *(const uint4*)&h_buf16[(size_t)gr * F2 + qc * 4];
            *(uint4*)&As[m * PITCH + qc * 8] = v;
        }
    }

    // ---- stage B (full 256x256, k-major rows) ----
    #pragma unroll
    for (int it = 0; it < 16; ++it) {
        int qidx = it * 512 + tid;
        int k  = qidx >> 5;
        int qc = qidx & 31;
        uint4 v = *(const uint4*)&Wb[(size_t)k * F2 + qc * 4];
        *(uint4*)&Bs[k * PITCH + qc * 8] = v;
    }
    __syncthreads();   // the ONLY barrier

    const unsigned asBase = (unsigned)__cvta_generic_to_shared(As);
    const unsigned bsBase = (unsigned)__cvta_generic_to_shared(Bs);
    const unsigned aOff =
        asBase + (unsigned)((warpM * 64 + (lane & 15)) * PITCH + (lane >> 4) * 8) * 2;
    const unsigned bOff =
        bsBase + (unsigned)((lane & 15) * PITCH + warpN * 32 + (lane >> 4) * 8) * 2;

    float acc[4][4][4];
    #pragma unroll
    for (int mi = 0; mi < 4; mi++)
        #pragma unroll
        for (int ni = 0; ni < 4; ni++)
            #pragma unroll
            for (int q = 0; q < 4; q++) acc[mi][ni][q] = 0.f;

    #pragma unroll 2
    for (int kt = 0; kt < F / 16; ++kt) {
        unsigned afr[4][4], bfr[2][4];
        const unsigned ak = aOff + (unsigned)(kt * 16) * 2;
        const unsigned bk = bOff + (unsigned)(kt * 16 * PITCH) * 2;
        #pragma unroll
        for (int mi = 0; mi < 4; mi++)
            ldsm_x4(afr[mi][0], afr[mi][1], afr[mi][2], afr[mi][3],
                    ak + (unsigned)(mi * 16 * PITCH) * 2);
        #pragma unroll
        for (int nb = 0; nb < 2; nb++)
            ldsm_x4_t(bfr[nb][0], bfr[nb][1], bfr[nb][2], bfr[nb][3],
                      bk + (unsigned)(nb * 16) * 2);
        #pragma unroll
        for (int mi = 0; mi < 4; mi++)
            #pragma unroll
            for (int ni = 0; ni < 4; ni++)
                mma_bf16(acc[mi][ni], afr[mi],
                         bfr[ni >> 1][(ni & 1) * 2], bfr[ni >> 1][(ni & 1) * 2 + 1]);
    }

    // ---- epilogue: store RAW bf16x2 (dinv applied in SpMM) ----
    const int g  = lane >> 2;
    const int tg = lane & 3;
    #pragma unroll
    for (int mi = 0; mi < 4; mi++) {
        int r0 = rowBase + warpM * 64 + mi * 16 + g;
        int r1 = r0 + 8;
        #pragma unroll
        for (int ni = 0; ni < 4; ni++) {
            int c = warpN * 32 + ni * 8 + 2 * tg;
            if (r0 < N_NODES)
                C[(size_t)r0 * F2 + (c >> 1)] =
                    pack_bf16(acc[mi][ni][0], acc[mi][ni][1]);
            if (r1 < N_NODES)
                C[(size_t)r1 * F2 + (c >> 1)] =
                    pack_bf16(acc[mi][ni][2], acc[mi][ni][3]);
        }
    }
}

// ---------------- SpMM: out[d] = dinv[d]*(Σ dinv[s]·g[s] + dinv[d]·g[d]) --
template <bool FINAL>
__global__ __launch_bounds__(128) void spmm_kernel(
        const float* __restrict__ bias,
        const float* __restrict__ xres,
        float* __restrict__ outp) {
    const int d = blockIdx.x;
    const int c = threadIdx.x;
    const unsigned* __restrict__ g = g_buf16;
    const int2* __restrict__ sw = g_srcw;

    const int s = g_rowstart[d];
    const int e = g_rowstart[d + 1];
    const float dd = g_dinv[d];

    float2 self = unpack_bf16(g[(size_t)d * F2 + c]);
    float2 acc = make_float2(dd * self.x, dd * self.y);   // self-loop term
    int j = s;
    for (; j + 4 <= e; j += 4) {
        int2 p0 = sw[j + 0];
        int2 p1 = sw[j + 1];
        int2 p2 = sw[j + 2];
        int2 p3 = sw[j + 3];
        float2 f0 = unpack_bf16(g[(size_t)p0.x * F2 + c]);
        float2 f1 = unpack_bf16(g[(size_t)p1.x * F2 + c]);
        float2 f2 = unpack_bf16(g[(size_t)p2.x * F2 + c]);
        float2 f3 = unpack_bf16(g[(size_t)p3.x * F2 + c]);
        float w0 = __int_as_float(p0.y), w1 = __int_as_float(p1.y);
        float w2 = __int_as_float(p2.y), w3 = __int_as_float(p3.y);
        acc.x = fmaf(w0, f0.x, acc.x); acc.y = fmaf(w0, f0.y, acc.y);
        acc.x = fmaf(w1, f1.x, acc.x); acc.y = fmaf(w1, f1.y, acc.y);
        acc.x = fmaf(w2, f2.x, acc.x); acc.y = fmaf(w2, f2.y, acc.y);
        acc.x = fmaf(w3, f3.x, acc.x); acc.y = fmaf(w3, f3.y, acc.y);
    }
    for (; j < e; ++j) {
        int2 p = sw[j];
        float2 f = unpack_bf16(g[(size_t)p.x * F2 + c]);
        float w = __int_as_float(p.y);
        acc.x = fmaf(w, f.x, acc.x); acc.y = fmaf(w, f.y, acc.y);
    }

    const float2 b = *(const float2*)&bias[2 * c];
    float r0 = fmaxf(dd * acc.x + b.x, 0.f);
    float r1 = fmaxf(dd * acc.y + b.y, 0.f);
    if (FINAL) {
        float2 xr = *(const float2*)&xres[(size_t)d * F + 2 * c];
        *(float2*)&outp[(size_t)d * F + 2 * c] =
            make_float2(0.5f * (xr.x + r0), 0.5f * (xr.y + r1));
    } else {
        h_buf16[(size_t)d * F2 + c] = pack_bf16(r0, r1);
    }
}

// ---------------- launch ---------------------------------------------------
extern "C" void kernel_launch(void* const* d_in, const int* in_sizes, int n_in,
                              void* d_out, int out_size) {
    const float* x  = (const float*)d_in[0];
    const int*   ei = (const int*)d_in[1];
    const float* W1 = (const float*)d_in[2];
    const float* b1 = (const float*)d_in[3];
    const float* W2 = (const float*)d_in[4];
    const float* b2 = (const float*)d_in[5];
    float* out = (float*)d_out;

    const int* srcp = ei;             // edge_index[0]
    const int* dstp = ei + N_EDGES;   // edge_index[1]

    const int TB = 256;
    const int nblk = (N_NODES + BM - 1) / BM;   // 391

    unsigned *wa_ptr = nullptr, *wb_ptr = nullptr;
    cudaGetSymbolAddress((void**)&wa_ptr, Wb16a);
    cudaGetSymbolAddress((void**)&wb_ptr, Wb16b);

    cudaFuncSetAttribute(gemm_bf16_kernel<1>,
                         cudaFuncAttributeMaxDynamicSharedMemorySize, SMEM_BYTES);
    cudaFuncSetAttribute(gemm_bf16_kernel<2>,
                         cudaFuncAttributeMaxDynamicSharedMemorySize, SMEM_BYTES);

    cudaStream_t s2 = 0;
    cudaEvent_t eF = 0, eJ = 0;
    bool forked =
        (cudaStreamCreateWithFlags(&s2, cudaStreamNonBlocking) == cudaSuccess) &&
        (cudaEventCreateWithFlags(&eF, cudaEventDisableTiming) == cudaSuccess) &&
        (cudaEventCreateWithFlags(&eJ, cudaEventDisableTiming) == cudaSuccess);

    if (forked) {
        // fork BEFORE any kernel: prep is independent of W conversion
        cudaEventRecord(eF, 0);
        cudaStreamWaitEvent(s2, eF, 0);

        w16_kernel<<<32, 1024>>>(W1, wa_ptr);                               // idx 1
        w16_kernel<<<32, 1024>>>(W2, wb_ptr);                               // idx 2
        init_counts_kernel<<<(N_NODES + TB - 1) / TB, TB, 0, s2>>>();       // idx 3
        hist_kernel<<<(N_EDGES + TB - 1) / TB, TB, 0, s2>>>(dstp);          // idx 4 (profiled)
        scanA_kernel<<<NCHUNK, 256, 0, s2>>>();                             // idx 5
        scanB_kernel<<<1, 256, 0, s2>>>();                                  // idx 6
        scanC_kernel<<<NCHUNK, 256, 0, s2>>>();                             // idx 7
        scatter_kernel<<<(N_EDGES + TB - 1) / TB, TB, 0, s2>>>(srcp, dstp); // idx 8
        gemm_bf16_kernel<1><<<nblk, 512, SMEM_BYTES>>>(x, wa_ptr);          // idx 9

        cudaEventRecord(eJ, s2);
        cudaStreamWaitEvent(0, eJ, 0);
        spmm_kernel<false><<<N_NODES, 128>>>(b1, nullptr, nullptr);         // idx 10
        gemm_bf16_kernel<2><<<nblk, 512, SMEM_BYTES>>>(nullptr, wb_ptr);    // idx 11
        spmm_kernel<true><<<N_NODES, 128>>>(b2, x, out);                    // idx 12
    } else {
        // serial fallback
        w16_kernel<<<32, 1024>>>(W1, wa_ptr);
        w16_kernel<<<32, 1024>>>(W2, wb_ptr);
        init_counts_kernel<<<(N_NODES + TB - 1) / TB, TB>>>();
        hist_kernel<<<(N_EDGES + TB - 1) / TB, TB>>>(dstp);
        scanA_kernel<<<NCHUNK, 256>>>();
        scanB_kernel<<<1, 256>>>();
        scanC_kernel<<<NCHUNK, 256>>>();
        scatter_kernel<<<(N_EDGES + TB - 1) / TB, TB>>>(srcp, dstp);
        gemm_bf16_kernel<1><<<nblk, 512, SMEM_BYTES>>>(x, wa_ptr);
        spmm_kernel<false><<<N_NODES, 128>>>(b1, nullptr, nullptr);
        gemm_bf16_kernel<2><<<nblk, 512, SMEM_BYTES>>>(nullptr, wb_ptr);
        spmm_kernel<true><<<N_NODES, 128>>>(b2, x, out);
    }
}

// round 13
// speedup vs baseline: 3.4559x; 1.3111x over previous
#include <cuda_runtime.h>
#include <cuda_bf16.h>
#include <cstdint>

#define N_NODES 50000
#define N_EDGES 800000
#define F 256
#define F2 (F / 2)
#define NCHUNK 196   // ceil(50000/256)

// ---------------- scratch (static device globals; no runtime alloc) -------
__device__ __align__(16) unsigned g_buf16[(size_t)N_NODES * F2];  // bf16x2 msgs (RAW)
__device__ __align__(16) unsigned h_buf16[(size_t)N_NODES * F2];  // bf16x2 acts
__device__ __align__(16) unsigned Wb16a[F * F2];                  // bf16x2 W1
__device__ __align__(16) unsigned Wb16b[F * F2];                  // bf16x2 W2
__device__ int   g_counts[N_NODES];
__device__ int   g_rowstart[N_NODES + 1];
__device__ int   g_cursor[N_NODES];
__device__ float g_dinv[N_NODES];
__device__ int   g_blocksum[NCHUNK];
__device__ __align__(16) int2 g_srcw[N_EDGES];    // (src, dinv[src] bits)

// ---------------- bf16 helpers ---------------------------------------------
__device__ __forceinline__ unsigned pack_bf16(float a, float b) {
    __nv_bfloat162 t = __floats2bfloat162_rn(a, b);
    return *(unsigned*)&t;
}

__device__ __forceinline__ float2 unpack_bf16(unsigned v) {
    __nv_bfloat162 t = *(__nv_bfloat162*)&v;
    return __bfloat1622float2(t);
}

// ---------------- prelude: W1/W2 -> bf16 AND zero counts (one kernel) ------
__global__ void prelude_kernel(const float* __restrict__ W1,
                               const float* __restrict__ W2) {
    int b = blockIdx.x;
    int t = threadIdx.x;
    if (b < 32) {
        int i = b * 1024 + t;                     // 0..32767
        float2 v = *(const float2*)&W1[2 * i];
        Wb16a[i] = pack_bf16(v.x, v.y);
    } else if (b < 64) {
        int i = (b - 32) * 1024 + t;
        float2 v = *(const float2*)&W2[2 * i];
        Wb16b[i] = pack_bf16(v.x, v.y);
    } else {
        int i = (b - 64) * 1024 + t;
        if (i < N_NODES) g_counts[i] = 0;
    }
}

// ---------------- graph preprocessing -------------------------------------
__global__ void hist_kernel(const int* __restrict__ dstp) {
    int e = blockIdx.x * blockDim.x + threadIdx.x;
    if (e < N_EDGES) atomicAdd(&g_counts[dstp[e]], 1);
}

__global__ void scanA_kernel() {   // per-chunk sums
    __shared__ int ws[8];
    int b = blockIdx.x;
    int i = b * 256 + threadIdx.x;
    int v = (i < N_NODES) ? g_counts[i] : 0;
    #pragma unroll
    for (int o = 16; o; o >>= 1) v += __shfl_down_sync(0xffffffffu, v, o);
    if ((threadIdx.x & 31) == 0) ws[threadIdx.x >> 5] = v;
    __syncthreads();
    if (threadIdx.x < 8) {
        int s = ws[threadIdx.x];
        #pragma unroll
        for (int o = 4; o; o >>= 1) s += __shfl_down_sync(0xffu, s, o);
        if (threadIdx.x == 0) g_blocksum[b] = s;
    }
}

// merged scanB+scanC: each block derives its own chunk offset by reducing
// the 196 chunk sums, then does the local exclusive scan + dinv/cursor.
__global__ void scanC2_kernel() {
    __shared__ int ws[8];
    __shared__ int soff;
    const int b = blockIdx.x;
    const int t = threadIdx.x;
    const int lane = t & 31, w = t >> 5;

    // chunk offset = sum of blocksums[j < b]
    int v2 = (t < b) ? g_blocksum[t] : 0;   // t<256, NCHUNK=196<=255
    #pragma unroll
    for (int o = 16; o; o >>= 1) v2 += __shfl_down_sync(0xffffffffu, v2, o);
    if (lane == 0) ws[w] = v2;
    __syncthreads();
    if (t < 8) {
        int s = ws[t];
        #pragma unroll
        for (int o = 4; o; o >>= 1) s += __shfl_down_sync(0xffu, s, o);
        if (t == 0) soff = s;
    }
    __syncthreads();
    const int chunkOff = soff;
    __syncthreads();   // ws reuse below

    // local exclusive scan of counts
    int i = b * 256 + t;
    int v = (i < N_NODES) ? g_counts[i] : 0;
    int incl = v;
    #pragma unroll
    for (int o = 1; o < 32; o <<= 1) {
        int x = __shfl_up_sync(0xffffffffu, incl, o);
        if (lane >= o) incl += x;
    }
    if (lane == 31) ws[w] = incl;
    __syncthreads();
    if (w == 0 && lane < 8) {
        int s = ws[lane];
        #pragma unroll
        for (int o = 1; o < 8; o <<= 1) {
            int x = __shfl_up_sync(0xffu, s, o);
            if (lane >= o) s += x;
        }
        ws[lane] = s;
    }
    __syncthreads();
    int woff = (w > 0) ? ws[w - 1] : 0;
    if (i < N_NODES) {
        int rs = chunkOff + woff + incl - v;
        g_rowstart[i] = rs;
        g_cursor[i]   = rs;
        g_dinv[i]     = rsqrtf((float)(v + 1));   // +1 self-loop
    }
    if (b == 0 && t == 0) g_rowstart[N_NODES] = N_EDGES;
}

__global__ void scatter_kernel(const int* __restrict__ srcp,
                               const int* __restrict__ dstp) {
    int e = blockIdx.x * blockDim.x + threadIdx.x;
    if (e < N_EDGES) {
        int s = srcp[e];
        int d = dstp[e];
        int pos = atomicAdd(&g_cursor[d], 1);
        g_srcw[pos] = make_int2(s, __float_as_int(g_dinv[s]));
    }
}

// ---------------- mma/ldsm helpers -----------------------------------------
__device__ __forceinline__ void ldsm_x4(unsigned& r0, unsigned& r1,
                                        unsigned& r2, unsigned& r3,
                                        unsigned addr) {
    asm volatile("ldmatrix.sync.aligned.m8n8.x4.shared.b16 {%0,%1,%2,%3}, [%4];"
                 : "=r"(r0), "=r"(r1), "=r"(r2), "=r"(r3) : "r"(addr));
}

__device__ __forceinline__ void ldsm_x4_t(unsigned& r0, unsigned& r1,
                                          unsigned& r2, unsigned& r3,
                                          unsigned addr) {
    asm volatile("ldmatrix.sync.aligned.m8n8.x4.trans.shared.b16 {%0,%1,%2,%3}, [%4];"
                 : "=r"(r0), "=r"(r1), "=r"(r2), "=r"(r3) : "r"(addr));
}

__device__ __forceinline__ void mma_bf16(float* c, const unsigned* a,
                                         unsigned b0, unsigned b1) {
    asm volatile(
        "mma.sync.aligned.m16n8k16.row.col.f32.bf16.bf16.f32 "
        "{%0,%1,%2,%3}, {%4,%5,%6,%7}, {%8,%9}, {%0,%1,%2,%3};\n"
        : "+f"(c[0]), "+f"(c[1]), "+f"(c[2]), "+f"(c[3])
        : "r"(a[0]), "r"(a[1]), "r"(a[2]), "r"(a[3]), "r"(b0), "r"(b1));
}

// ---------------- GEMM (bf16 mma.sync, smem-resident, frag double-buffer) --
#define BM 128
#define BN 256
#define PITCH 264   // ushorts: 528B rows -> 33r mod 8 = r (conflict-free)
#define SMEM_A_WORDS (BM * PITCH)
#define SMEM_B_WORDS (F * PITCH)
#define SMEM_BYTES ((SMEM_A_WORDS + SMEM_B_WORDS) * 2)   // 202752 B

template <int LAYER>
__global__ __launch_bounds__(512) void gemm_bf16_kernel(
        const float* __restrict__ Ain, const unsigned* __restrict__ Wb) {
    extern __shared__ __align__(16) unsigned short sm[];
    unsigned short* As = sm;                    // [128][PITCH]
    unsigned short* Bs = sm + SMEM_A_WORDS;     // [256][PITCH] (k-major)

    unsigned* __restrict__ C = g_buf16;

    const int tid   = threadIdx.x;
    const int lane  = tid & 31;
    const int warp  = tid >> 5;
    const int warpM = warp & 1;
    const int warpN = warp >> 1;
    const int rowBase = blockIdx.x * BM;

    // ---- stage A (full 128x256) ----
    if (LAYER == 1) {
        #pragma unroll
        for (int it = 0; it < 16; ++it) {
            int fidx = it * 512 + tid;
            int m  = fidx >> 6;
            int fc = fidx & 63;
            int gr = rowBase + m;
            float4 v = make_float4(0.f, 0.f, 0.f, 0.f);
            if (gr < N_NODES) v = *(const float4*)&Ain[(size_t)gr * F + fc * 4];
            uint2 pv;
            pv.x = pack_bf16(v.x, v.y);
            pv.y = pack_bf16(v.z, v.w);
            *(uint2*)&As[m * PITCH + fc * 4] = pv;
        }
    } else {
        #pragma unroll
        for (int it = 0; it < 8; ++it) {
            int qidx = it * 512 + tid;
            int m  = qidx >> 5;
            int qc = qidx & 31;
            int gr = rowBase + m;
            uint4 v = make_uint4(0u, 0u, 0u, 0u);
            if (gr < N_NODES) v = *(const uint4*)&h_buf16[(size_t)gr * F2 + qc * 4];
            *(uint4*)&As[m * PITCH + qc * 8] = v;
        }
    }

    // ---- stage B (full 256x256, k-major rows) ----
    #pragma unroll
    for (int it = 0; it < 16; ++it) {
        int qidx = it * 512 + tid;
        int k  = qidx >> 5;
        int qc = qidx & 31;
        uint4 v = *(const uint4*)&Wb[(size_t)k * F2 + qc * 4];
        *(uint4*)&Bs[k * PITCH + qc * 8] = v;
    }
    __syncthreads();   // the ONLY barrier

    const unsigned asBase = (unsigned)__cvta_generic_to_shared(As);
    const unsigned bsBase = (unsigned)__cvta_generic_to_shared(Bs);
    const unsigned aOff =
        asBase + (unsigned)((warpM * 64 + (lane & 15)) * PITCH + (lane >> 4) * 8) * 2;
    const unsigned bOff =
        bsBase + (unsigned)((lane & 15) * PITCH + warpN * 32 + (lane >> 4) * 8) * 2;

    float acc[4][4][4];
    #pragma unroll
    for (int mi = 0; mi < 4; mi++)
        #pragma unroll
        for (int ni = 0; ni < 4; ni++)
            #pragma unroll
            for (int q = 0; q < 4; q++) acc[mi][ni][q] = 0.f;

    // fragment double-buffer: prefetch k-step kt+1 while kt's MMAs issue
    unsigned afr[2][4][4], bfr[2][2][4];

    #define LD_FRAGS(buf, kt)                                                   \
        do {                                                                    \
            const unsigned _ak = aOff + (unsigned)((kt) * 16) * 2;              \
            const unsigned _bk = bOff + (unsigned)((kt) * 16 * PITCH) * 2;      \
            _Pragma("unroll")                                                   \
            for (int mi = 0; mi < 4; mi++)                                      \
                ldsm_x4(afr[buf][mi][0], afr[buf][mi][1],                       \
                        afr[buf][mi][2], afr[buf][mi][3],                       \
                        _ak + (unsigned)(mi * 16 * PITCH) * 2);                 \
            _Pragma("unroll")                                                   \
            for (int nb = 0; nb < 2; nb++)                                      \
                ldsm_x4_t(bfr[buf][nb][0], bfr[buf][nb][1],                     \
                          bfr[buf][nb][2], bfr[buf][nb][3],                     \
                          _bk + (unsigned)(nb * 16) * 2);                       \
        } while (0)

    LD_FRAGS(0, 0);
    #pragma unroll
    for (int kt = 0; kt < F / 16; ++kt) {
        const int cur = kt & 1;
        if (kt < F / 16 - 1) LD_FRAGS(cur ^ 1, kt + 1);
        #pragma unroll
        for (int mi = 0; mi < 4; mi++)
            #pragma unroll
            for (int ni = 0; ni < 4; ni++)
                mma_bf16(acc[mi][ni], afr[cur][mi],
                         bfr[cur][ni >> 1][(ni & 1) * 2],
                         bfr[cur][ni >> 1][(ni & 1) * 2 + 1]);
    }
    #undef LD_FRAGS

    // ---- epilogue: store RAW bf16x2 (dinv applied in SpMM) ----
    const int g  = lane >> 2;
    const int tg = lane & 3;
    #pragma unroll
    for (int mi = 0; mi < 4; mi++) {
        int r0 = rowBase + warpM * 64 + mi * 16 + g;
        int r1 = r0 + 8;
        #pragma unroll
        for (int ni = 0; ni < 4; ni++) {
            int c = warpN * 32 + ni * 8 + 2 * tg;
            if (r0 < N_NODES)
                C[(size_t)r0 * F2 + (c >> 1)] =
                    pack_bf16(acc[mi][ni][0], acc[mi][ni][1]);
            if (r1 < N_NODES)
                C[(size_t)r1 * F2 + (c >> 1)] =
                    pack_bf16(acc[mi][ni][2], acc[mi][ni][3]);
        }
    }
}

// ---------------- SpMM: out[d] = dinv[d]*(Σ dinv[s]·g[s] + dinv[d]·g[d]) --
// 2 nodes per 128-thread block; 64 threads per node; thread owns one uint2
// (= 4 bf16 cols) -> LDG.64 gathers (half the instruction count of LDG.32).
template <bool FINAL>
__global__ __launch_bounds__(128) void spmm_kernel(
        const float* __restrict__ bias,
        const float* __restrict__ xres,
        float* __restrict__ outp) {
    const int d = blockIdx.x * 2 + (threadIdx.x >> 6);
    const int t = threadIdx.x & 63;                    // uint2 index in row
    const uint2* __restrict__ g2 = (const uint2*)g_buf16;   // row = 64 uint2
    const int2* __restrict__ sw = g_srcw;

    const int s = g_rowstart[d];
    const int e = g_rowstart[d + 1];
    const float dd = g_dinv[d];

    uint2 sv = g2[(size_t)d * 64 + t];
    float2 s0 = unpack_bf16(sv.x), s1 = unpack_bf16(sv.y);
    float4 acc = make_float4(dd * s0.x, dd * s0.y, dd * s1.x, dd * s1.y);

    int j = s;
    for (; j + 4 <= e; j += 4) {
        int2 p0 = sw[j + 0];
        int2 p1 = sw[j + 1];
        int2 p2 = sw[j + 2];
        int2 p3 = sw[j + 3];
        uint2 v0 = g2[(size_t)p0.x * 64 + t];
        uint2 v1 = g2[(size_t)p1.x * 64 + t];
        uint2 v2 = g2[(size_t)p2.x * 64 + t];
        uint2 v3 = g2[(size_t)p3.x * 64 + t];
        float w0 = __int_as_float(p0.y), w1 = __int_as_float(p1.y);
        float w2 = __int_as_float(p2.y), w3 = __int_as_float(p3.y);
        float2 a, b;
        a = unpack_bf16(v0.x); b = unpack_bf16(v0.y);
        acc.x = fmaf(w0, a.x, acc.x); acc.y = fmaf(w0, a.y, acc.y);
        acc.z = fmaf(w0, b.x, acc.z); acc.w = fmaf(w0, b.y, acc.w);
        a = unpack_bf16(v1.x); b = unpack_bf16(v1.y);
        acc.x = fmaf(w1, a.x, acc.x); acc.y = fmaf(w1, a.y, acc.y);
        acc.z = fmaf(w1, b.x, acc.z); acc.w = fmaf(w1, b.y, acc.w);
        a = unpack_bf16(v2.x); b = unpack_bf16(v2.y);
        acc.x = fmaf(w2, a.x, acc.x); acc.y = fmaf(w2, a.y, acc.y);
        acc.z = fmaf(w2, b.x, acc.z); acc.w = fmaf(w2, b.y, acc.w);
        a = unpack_bf16(v3.x); b = unpack_bf16(v3.y);
        acc.x = fmaf(w3, a.x, acc.x); acc.y = fmaf(w3, a.y, acc.y);
        acc.z = fmaf(w3, b.x, acc.z); acc.w = fmaf(w3, b.y, acc.w);
    }
    for (; j < e; ++j) {
        int2 p = sw[j];
        uint2 v = g2[(size_t)p.x * 64 + t];
        float w = __int_as_float(p.y);
        float2 a = unpack_bf16(v.x), b = unpack_bf16(v.y);
        acc.x = fmaf(w, a.x, acc.x); acc.y = fmaf(w, a.y, acc.y);
        acc.z = fmaf(w, b.x, acc.z); acc.w = fmaf(w, b.y, acc.w);
    }

    const float4 bv = ((const float4*)bias)[t];
    float r0 = fmaxf(dd * acc.x + bv.x, 0.f);
    float r1 = fmaxf(dd * acc.y + bv.y, 0.f);
    float r2 = fmaxf(dd * acc.z + bv.z, 0.f);
    float r3 = fmaxf(dd * acc.w + bv.w, 0.f);
    if (FINAL) {
        const float4 xr = ((const float4*)xres)[(size_t)d * 64 + t];
        float4 o;
        o.x = 0.5f * (xr.x + r0);
        o.y = 0.5f * (xr.y + r1);
        o.z = 0.5f * (xr.z + r2);
        o.w = 0.5f * (xr.w + r3);
        ((float4*)outp)[(size_t)d * 64 + t] = o;
    } else {
        uint2 hv;
        hv.x = pack_bf16(r0, r1);
        hv.y = pack_bf16(r2, r3);
        ((uint2*)h_buf16)[(size_t)d * 64 + t] = hv;
    }
}

// ---------------- launch ---------------------------------------------------
extern "C" void kernel_launch(void* const* d_in, const int* in_sizes, int n_in,
                              void* d_out, int out_size) {
    const float* x  = (const float*)d_in[0];
    const int*   ei = (const int*)d_in[1];
    const float* W1 = (const float*)d_in[2];
    const float* b1 = (const float*)d_in[3];
    const float* W2 = (const float*)d_in[4];
    const float* b2 = (const float*)d_in[5];
    float* out = (float*)d_out;

    const int* srcp = ei;             // edge_index[0]
    const int* dstp = ei + N_EDGES;   // edge_index[1]

    const int TB = 256;
    const int nblk = (N_NODES + BM - 1) / BM;   // 391

    unsigned *wa_ptr = nullptr, *wb_ptr = nullptr;
    cudaGetSymbolAddress((void**)&wa_ptr, Wb16a);
    cudaGetSymbolAddress((void**)&wb_ptr, Wb16b);

    cudaFuncSetAttribute(gemm_bf16_kernel<1>,
                         cudaFuncAttributeMaxDynamicSharedMemorySize, SMEM_BYTES);
    cudaFuncSetAttribute(gemm_bf16_kernel<2>,
                         cudaFuncAttributeMaxDynamicSharedMemorySize, SMEM_BYTES);

    cudaStream_t s2 = 0;
    cudaEvent_t eF = 0, eJ = 0;
    bool forked =
        (cudaStreamCreateWithFlags(&s2, cudaStreamNonBlocking) == cudaSuccess) &&
        (cudaEventCreateWithFlags(&eF, cudaEventDisableTiming) == cudaSuccess) &&
        (cudaEventCreateWithFlags(&eJ, cudaEventDisableTiming) == cudaSuccess);

    if (forked) {
        prelude_kernel<<<113, 1024>>>(W1, W2);                              // W->bf16 + zero counts
        cudaEventRecord(eF, 0);
        cudaStreamWaitEvent(s2, eF, 0);

        gemm_bf16_kernel<1><<<nblk, 512, SMEM_BYTES>>>(x, wa_ptr);          // main
        hist_kernel<<<(N_EDGES + TB - 1) / TB, TB, 0, s2>>>(dstp);          // s2 (hidden)
        scanA_kernel<<<NCHUNK, 256, 0, s2>>>();
        scanC2_kernel<<<NCHUNK, 256, 0, s2>>>();
        scatter_kernel<<<(N_EDGES + TB - 1) / TB, TB, 0, s2>>>(srcp, dstp);

        cudaEventRecord(eJ, s2);
        cudaStreamWaitEvent(0, eJ, 0);
        spmm_kernel<false><<<N_NODES / 2, 128>>>(b1, nullptr, nullptr);
        gemm_bf16_kernel<2><<<nblk, 512, SMEM_BYTES>>>(nullptr, wb_ptr);
        spmm_kernel<true><<<N_NODES / 2, 128>>>(b2, x, out);
    } else {
        // serial fallback
        prelude_kernel<<<113, 1024>>>(W1, W2);
        hist_kernel<<<(N_EDGES + TB - 1) / TB, TB>>>(dstp);
        scanA_kernel<<<NCHUNK, 256>>>();
        scanC2_kernel<<<NCHUNK, 256>>>();
        scatter_kernel<<<(N_EDGES + TB - 1) / TB, TB>>>(srcp, dstp);
        gemm_bf16_kernel<1><<<nblk, 512, SMEM_BYTES>>>(x, wa_ptr);
        spmm_kernel<false><<<N_NODES / 2, 128>>>(b1, nullptr, nullptr);
        gemm_bf16_kernel<2><<<nblk, 512, SMEM_BYTES>>>(nullptr, wb_ptr);
        spmm_kernel<true><<<N_NODES / 2, 128>>>(b2, x, out);
    }
}